// round 12
// baseline (speedup 1.0000x reference)
#include <cuda_runtime.h>
#include <cuda_bf16.h>
#include <math.h>
#include <stdint.h>

#define Bv 1024
#define Tv 16
#define Vv 8000
#define VP 8064                    // 8064 = 84*96 (tiles exactly)
#define Ev 256
#define Hv 512
#define H3 1536

// ---------------- scratch (static device globals) ----------------------------
__device__ __nv_bfloat16 g_Xb[Tv * Bv * Ev];           // gathered inputs (bf16)
__device__ float g_GI[(size_t)Tv * Bv * H3];           // permuted input gates
__device__ float g_Hall[Tv * Bv * Hv];                 // hidden states (fp32 carry)
__device__ __nv_bfloat16 g_Hbf[(Tv + 1) * Bv * Hv];    // slice0=context, t+1=step t
__device__ __nv_bfloat16 g_Wih_b[H3 * Ev];             // permuted W_ih (bf16)
__device__ __nv_bfloat16 g_Whh_b[H3 * Hv];             // permuted W_hh (bf16)
__device__ __nv_bfloat16 g_Wout_b[VP * Hv];            // out_W (bf16, zero-padded)
__device__ __nv_bfloat16 g_Lbf[(size_t)Tv * Bv * VP];  // bf16 logits, 264 MB
__device__ float g_bih_p[H3];
__device__ float g_bhh_p[H3];

// ---------------- helpers ------------------------------------------------------
__device__ __forceinline__ uint32_t smem_u32(const void* p) {
    uint32_t a;
    asm("{ .reg .u64 t; cvta.to.shared.u64 t, %1; cvt.u32.u64 %0, t; }"
        : "=r"(a) : "l"(p));
    return a;
}
__device__ __forceinline__ uint32_t f2bf2(float lo, float hi) {
    uint32_t r;
    asm("cvt.rn.bf16x2.f32 %0, %1, %2;" : "=r"(r) : "f"(hi), "f"(lo));
    return r;
}
__device__ __forceinline__ void cp_async16(uint32_t dst, const void* src, uint32_t sz) {
    asm volatile("cp.async.cg.shared.global [%0], [%1], 16, %2;"
                 :: "r"(dst), "l"(src), "r"(sz) : "memory");
}
__device__ __forceinline__ void cp_commit() {
    asm volatile("cp.async.commit_group;" ::: "memory");
}
__device__ __forceinline__ void cp_wait1() {
    asm volatile("cp.async.wait_group 1;" ::: "memory");
}
__device__ __forceinline__ void ldm_x4(uint32_t* r, uint32_t addr) {
    asm volatile("ldmatrix.sync.aligned.m8n8.x4.shared.b16 {%0,%1,%2,%3}, [%4];"
                 : "=r"(r[0]), "=r"(r[1]), "=r"(r[2]), "=r"(r[3]) : "r"(addr));
}
__device__ __forceinline__ void ldm_x2(uint32_t* r, uint32_t addr) {
    asm volatile("ldmatrix.sync.aligned.m8n8.x2.shared.b16 {%0,%1}, [%2];"
                 : "=r"(r[0]), "=r"(r[1]) : "r"(addr));
}
__device__ __forceinline__ void mma_bf16(float* c, const uint32_t* a, const uint32_t* b) {
    asm volatile(
        "mma.sync.aligned.m16n8k16.row.col.f32.bf16.bf16.f32 "
        "{%0,%1,%2,%3}, {%4,%5,%6,%7}, {%8,%9}, {%0,%1,%2,%3};"
        : "+f"(c[0]), "+f"(c[1]), "+f"(c[2]), "+f"(c[3])
        : "r"(a[0]), "r"(a[1]), "r"(a[2]), "r"(a[3]), "r"(b[0]), "r"(b[1]));
}
__device__ __forceinline__ void stcs_f2(float* p, float x, float y) {
    asm volatile("st.global.cs.v2.f32 [%0], {%1, %2};" :: "l"(p), "f"(x), "f"(y)
                 : "memory");
}
__device__ __forceinline__ void stcs_u32(uint32_t* p, uint32_t v) {
    asm volatile("st.global.cs.u32 [%0], %1;" :: "l"(p), "r"(v) : "memory");
}
__device__ __forceinline__ float sigm(float x) { return 1.f / (1.f + expf(-x)); }

// ========== bf16 GEMM: 128 threads, BM=128, BN=96, BK=64, 2-stage ==============
// Warp grid 2x2, warp tile 64x48. 64.5 KB smem, ~168 regs -> 3 CTAs/SM.
// MODE 0: fp32 out + bias (GI).
// MODE 1: bf16 out + bias, stride VP, no remap/guard (logits intermediate).
template <int MODE>
__global__ void __launch_bounds__(128, 3)
bf_gemm(const __nv_bfloat16* __restrict__ A, const __nv_bfloat16* __restrict__ W,
        const float* __restrict__ bias, float* __restrict__ C,
        int M, int N, int Nv_, int K) {
    constexpr int BM = 128, BN = 96;
    constexpr int RSTR = 36;                 // u32 per smem row (32 data + 4 pad)
    constexpr int ASTG = BM * RSTR;
    constexpr int BSTG = BN * RSTR;
    constexpr int STG = ASTG + BSTG;         // one stage (A then B)

    extern __shared__ uint32_t smu[];
    const uint32_t sS = smem_u32(smu);       // stage0 base; stage1 at +STG*4

    const int tid = threadIdx.x;
    const int wid = tid >> 5, lane = tid & 31;
    const int grp = lane >> 2, tig = lane & 3;
    const int warpRow = wid & 1, warpCol = wid >> 1;   // 2 x 2, warp tile 64x48
    const int mBase = blockIdx.y * BM;
    const int nBase = blockIdx.x * BN;

    auto load_stage = [&](int s, int kc) {
        const int k0 = kc * 64;
        const uint32_t base = sS + s * STG * 4;
#pragma unroll
        for (int i = 0; i < 8; i++) {                   // A: 1024 x 16B
            int idx = i * 128 + tid;
            int row = idx >> 3, c = idx & 7;
            cp_async16(base + (row * RSTR + c * 4) * 4,
                       A + (size_t)(mBase + row) * K + k0 + c * 8, 16);
        }
#pragma unroll
        for (int i = 0; i < 6; i++) {                   // B: 768 x 16B (N padded)
            int idx = i * 128 + tid;
            int row = idx >> 3, c = idx & 7;
            cp_async16(base + (ASTG + row * RSTR + c * 4) * 4,
                       W + (size_t)(nBase + row) * K + k0 + c * 8, 16);
        }
    };

    const int a_r = lane & 15, a_c = (lane >> 4) * 4;
    const int b_r = (lane >> 4) * 8 + (lane & 7), b_c = ((lane >> 3) & 1) * 4;
    uint32_t aOff[4], bOff[3];
#pragma unroll
    for (int mt = 0; mt < 4; mt++)
        aOff[mt] = ((warpRow * 64 + mt * 16 + a_r) * RSTR + a_c) * 4;
#pragma unroll
    for (int nb = 0; nb < 3; nb++)
        bOff[nb] = ((ASTG + (warpCol * 48 + nb * 16 + b_r) * RSTR + b_c)) * 4;

    float acc[4][6][4];
#pragma unroll
    for (int mt = 0; mt < 4; mt++)
#pragma unroll
        for (int nt = 0; nt < 6; nt++)
#pragma unroll
            for (int j = 0; j < 4; j++) acc[mt][nt][j] = 0.f;

    const int nk = K >> 6;
    load_stage(0, 0); cp_commit();
    load_stage(1, 1); cp_commit();

    for (int k = 0; k < nk; k++) {
        cp_wait1();                          // chunk k resident
        __syncthreads();
        const uint32_t st = sS + (k & 1) * STG * 4;
#pragma unroll
        for (int kk = 0; kk < 4; kk++) {     // four k16 slices (32B apart)
            uint32_t a[4][4], b[3][4];
#pragma unroll
            for (int mt = 0; mt < 4; mt++) ldm_x4(a[mt], st + aOff[mt] + kk * 32);
#pragma unroll
            for (int nb = 0; nb < 3; nb++) ldm_x4(b[nb], st + bOff[nb] + kk * 32);
#pragma unroll
            for (int mt = 0; mt < 4; mt++)
#pragma unroll
                for (int nt = 0; nt < 6; nt++)
                    mma_bf16(acc[mt][nt], a[mt], &b[nt >> 1][(nt & 1) * 2]);
        }
        __syncthreads();                     // all reads of buf k&1 done
        if (k + 2 < nk) { load_stage(k & 1, k + 2); }
        cp_commit();                         // keep group count in lockstep
    }

    // ---------------- epilogue ----------------
    if constexpr (MODE == 0) {               // fp32 + bias, stride Nv_
#pragma unroll
        for (int mt = 0; mt < 4; mt++) {
            const int m0 = mBase + warpRow * 64 + mt * 16 + grp;
            const int m1 = m0 + 8;
            float* c0 = C + (size_t)m0 * Nv_;
            float* c1 = C + (size_t)m1 * Nv_;
#pragma unroll
            for (int nt = 0; nt < 6; nt++) {
                const int n = nBase + warpCol * 48 + nt * 8 + tig * 2;
                float2 bv = *(const float2*)(bias + n);
                stcs_f2(c0 + n, acc[mt][nt][0] + bv.x, acc[mt][nt][1] + bv.y);
                stcs_f2(c1 + n, acc[mt][nt][2] + bv.x, acc[mt][nt][3] + bv.y);
            }
        }
    } else {                                 // bf16 + bias, stride VP, padded
        __nv_bfloat16* Cb = (__nv_bfloat16*)C;
#pragma unroll
        for (int mt = 0; mt < 4; mt++) {
            const int m0 = mBase + warpRow * 64 + mt * 16 + grp;
            const int m1 = m0 + 8;
            uint32_t* c0 = (uint32_t*)(Cb + (size_t)m0 * VP);
            uint32_t* c1 = (uint32_t*)(Cb + (size_t)m1 * VP);
#pragma unroll
            for (int nt = 0; nt < 6; nt++) {
                const int n = nBase + warpCol * 48 + nt * 8 + tig * 2;
                float2 bv = *(const float2*)(bias + n);
                stcs_u32(c0 + (n >> 1),
                         f2bf2(acc[mt][nt][0] + bv.x, acc[mt][nt][1] + bv.y));
                stcs_u32(c1 + (n >> 1),
                         f2bf2(acc[mt][nt][2] + bv.x, acc[mt][nt][3] + bv.y));
            }
        }
    }
}

// ================== bf16 recurrence GEMM + fused GRU gates =====================
// BM=64, BN=96 ([r32|z32|n32]), BK=64; grid (16,16) = 256 CTAs, 69 KB smem.
__global__ void __launch_bounds__(256)
rec_step(const __nv_bfloat16* __restrict__ A, const __nv_bfloat16* __restrict__ W,
         const float* __restrict__ gi, const float* __restrict__ hpf,
         float* __restrict__ hout, __nv_bfloat16* __restrict__ hbf,
         const float* __restrict__ bhh) {
    constexpr int STAGES = 3, RSTR = 36;
    constexpr int ASTG = 64 * RSTR, BSTG = 96 * RSTR;
    constexpr int K = Hv;

    extern __shared__ uint32_t smu[];
    const uint32_t sA = smem_u32(smu);
    const uint32_t sB = sA + STAGES * ASTG * 4;

    const int tid = threadIdx.x;
    const int wid = tid >> 5, lane = tid & 31;
    const int grp = lane >> 2, tig = lane & 3;
    const int warpRow = wid >> 2, warpCol = wid & 3;   // 2 x 4, warp tile 32x24
    const int mBase = blockIdx.y * 64;
    const int nBase = blockIdx.x * 96;

    auto load_stage = [&](int s, int kc) {
        const int k0 = kc * 64;
#pragma unroll
        for (int i = 0; i < 2; i++) {                   // A: 512 x 16B
            int idx = i * 256 + tid;
            int row = idx >> 3, c = idx & 7;
            cp_async16(sA + (s * ASTG + row * RSTR + c * 4) * 4,
                       A + (size_t)(mBase + row) * K + k0 + c * 8, 16);
        }
#pragma unroll
        for (int i = 0; i < 3; i++) {                   // B: 768 x 16B
            int idx = i * 256 + tid;
            int row = idx >> 3, c = idx & 7;
            cp_async16(sB + (s * BSTG + row * RSTR + c * 4) * 4,
                       W + (size_t)(nBase + row) * K + k0 + c * 8, 16);
        }
    };

    const int a_r = lane & 15, a_c = (lane >> 4) * 4;
    const int b_r = (lane >> 4) * 8 + (lane & 7), b_c = ((lane >> 3) & 1) * 4;
    const int b2_r = lane & 7, b2_c = ((lane >> 3) & 1) * 4;   // x2 (lanes 0-15)
    uint32_t aOff[2], bOff, b2Off;
#pragma unroll
    for (int mt = 0; mt < 2; mt++)
        aOff[mt] = ((warpRow * 32 + mt * 16 + a_r) * RSTR + a_c) * 4;
    bOff  = ((warpCol * 24 + b_r) * RSTR + b_c) * 4;
    b2Off = ((warpCol * 24 + 16 + b2_r) * RSTR + b2_c) * 4;

    float acc[2][3][4];
#pragma unroll
    for (int mt = 0; mt < 2; mt++)
#pragma unroll
        for (int nt = 0; nt < 3; nt++)
#pragma unroll
            for (int j = 0; j < 4; j++) acc[mt][nt][j] = 0.f;

    const int nk = K >> 6;                    // 8
    load_stage(0, 0); cp_commit();
    load_stage(1, 1); cp_commit();

    for (int k = 0; k < nk; k++) {
        const int s = k % STAGES;
        cp_wait1();
        __syncthreads();
        if (k + 2 < nk) load_stage((k + 2) % STAGES, k + 2);
        cp_commit();

        const uint32_t aS = sA + s * ASTG * 4;
        const uint32_t bS = sB + s * BSTG * 4;
#pragma unroll
        for (int kk = 0; kk < 4; kk++) {
            uint32_t a[2][4], b01[4], b2[2];
#pragma unroll
            for (int mt = 0; mt < 2; mt++) ldm_x4(a[mt], aS + aOff[mt] + kk * 32);
            ldm_x4(b01, bS + bOff + kk * 32);
            ldm_x2(b2, bS + b2Off + kk * 32);
#pragma unroll
            for (int mt = 0; mt < 2; mt++) {
                mma_bf16(acc[mt][0], a[mt], &b01[0]);
                mma_bf16(acc[mt][1], a[mt], &b01[2]);
                mma_bf16(acc[mt][2], a[mt], b2);
            }
        }
    }

    // -------- epilogue: stage GH to smem, fused gate math --------
    constexpr int GSTR = 100;
    float* gh = (float*)smu;
    asm volatile("cp.async.wait_all;" ::: "memory");
    __syncthreads();
#pragma unroll
    for (int mt = 0; mt < 2; mt++) {
        const int r0 = warpRow * 32 + mt * 16 + grp;
#pragma unroll
        for (int nt = 0; nt < 3; nt++) {
            const int n = warpCol * 24 + nt * 8 + tig * 2;
            gh[r0 * GSTR + n] = acc[mt][nt][0];
            gh[r0 * GSTR + n + 1] = acc[mt][nt][1];
            gh[(r0 + 8) * GSTR + n] = acc[mt][nt][2];
            gh[(r0 + 8) * GSTR + n + 1] = acc[mt][nt][3];
        }
    }
    __syncthreads();
    const int qBase = nBase / 3;              // nBase = bx*96 -> q base = bx*32
#pragma unroll
    for (int i = 0; i < 8; i++) {
        const int idx = i * 256 + tid;        // 0..2047
        const int row = idx >> 5;
        const int q = idx & 31;
        const int m = mBase + row;
        const float ghr = gh[row * GSTR + q] + bhh[nBase + q];
        const float ghz = gh[row * GSTR + 32 + q] + bhh[nBase + 32 + q];
        const float ghn = gh[row * GSTR + 64 + q] + bhh[nBase + 64 + q];
        const float* girow = gi + (size_t)m * H3 + nBase;
        const float r = sigm(girow[q] + ghr);
        const float z = sigm(girow[32 + q] + ghz);
        const float n = tanhf(girow[64 + q] + r * ghn);
        const int qg = qBase + q;
        const float hp = hpf[(size_t)m * Hv + qg];
        const float h = (1.f - z) * n + z * hp;
        hout[(size_t)m * Hv + qg] = h;
        hbf[(size_t)m * Hv + qg] = __float2bfloat16(h);
    }
}

// ---------------- prep kernels -------------------------------------------------
__global__ void gather_x(const float* __restrict__ embed,
                         const int* __restrict__ target) {
    int row = blockIdx.x;              // row = t*B + b
    int t = row >> 10;
    int b = row & (Bv - 1);
    int idx = (t == 0) ? 0 : target[b * Tv + (t - 1)];
    float4 v = ((const float4*)(embed + (size_t)idx * Ev))[threadIdx.x];
    uint2 o = make_uint2(f2bf2(v.x, v.y), f2bf2(v.z, v.w));
    ((uint2*)(g_Xb + (size_t)row * Ev))[threadIdx.x] = o;
}

__global__ void permute_w(const float* __restrict__ Wih, const float* __restrict__ Whh,
                          const float* __restrict__ bih, const float* __restrict__ bhh) {
    int p = blockIdx.x;                // 0..1535
    int T = p / 96, local = p - T * 96;
    int gate = local / 32, q = T * 32 + (local - gate * 32);
    int src = gate * Hv + q;
    int t = threadIdx.x;               // 128 threads
    if (t < 64) {
        float4 v = ((const float4*)(Wih + (size_t)src * Ev))[t];
        ((uint2*)(g_Wih_b + (size_t)p * Ev))[t] =
            make_uint2(f2bf2(v.x, v.y), f2bf2(v.z, v.w));
    }
    float4 w = ((const float4*)(Whh + (size_t)src * Hv))[t];
    ((uint2*)(g_Whh_b + (size_t)p * Hv))[t] =
        make_uint2(f2bf2(w.x, w.y), f2bf2(w.z, w.w));
    if (t == 0) { g_bih_p[p] = bih[src]; g_bhh_p[p] = bhh[src]; }
}

// convert out_W to bf16; zero-pad rows [Vv, VP)
__global__ void conv_outw(const float* __restrict__ W) {
    size_t i = ((size_t)blockIdx.x * 256 + threadIdx.x) * 4;   // over VP*Hv
    uint2 o = make_uint2(0u, 0u);
    if (i < (size_t)Vv * Hv) {
        float4 v = *(const float4*)(W + i);
        o = make_uint2(f2bf2(v.x, v.y), f2bf2(v.z, v.w));
    }
    *(uint2*)(g_Wout_b + i) = o;
}

__global__ void conv_ctx(const float* __restrict__ ctx) {
    size_t i = ((size_t)blockIdx.x * 256 + threadIdx.x) * 4;
    float4 v = *(const float4*)(ctx + i);
    *(uint2*)(g_Hbf + i) = make_uint2(f2bf2(v.x, v.y), f2bf2(v.z, v.w));
}

// -------- log-softmax: bf16 logits in (t*B+b layout), fp32 logprobs out --------
__global__ void __launch_bounds__(256)
logsoftmax_rows(const __nv_bfloat16* __restrict__ Lbf, float* __restrict__ out) {
    extern __shared__ float rowc[];     // 8000 floats
    __shared__ float sm[256], ss[256];
    const int tid = threadIdx.x;
    const int ro = blockIdx.x;          // output row index (b*T + t)
    const int b = ro >> 4, t = ro & 15;
    const uint32_t* src = (const uint32_t*)(Lbf + (size_t)(t * Bv + b) * VP);

    float m = -INFINITY, s = 0.f;
    for (int i = tid; i < Vv / 2; i += 256) {
        uint32_t u = src[i];
        float lo = __uint_as_float(u << 16);
        float hi = __uint_as_float(u & 0xffff0000u);
        rowc[2 * i] = lo;
        rowc[2 * i + 1] = hi;
        float mx = fmaxf(lo, hi);
        if (mx > m) { s *= expf(m - mx); m = mx; }
        s += expf(lo - m) + expf(hi - m);
    }
    sm[tid] = m; ss[tid] = s;
    __syncthreads();
    for (int st = 128; st > 0; st >>= 1) {
        if (tid < st) {
            float m2 = sm[tid + st], s2 = ss[tid + st];
            float M = fmaxf(sm[tid], m2);
            ss[tid] = ss[tid] * expf(sm[tid] - M) + s2 * expf(m2 - M);
            sm[tid] = M;
        }
        __syncthreads();
    }
    const float lse = sm[0] + logf(ss[0]);
    float4* dst = (float4*)(out + (size_t)ro * Vv);
    for (int i = tid; i < Vv / 4; i += 256) {
        float4 x = ((const float4*)rowc)[i];
        dst[i] = make_float4(x.x - lse, x.y - lse, x.z - lse, x.w - lse);
    }
}

// ---------------- launch --------------------------------------------------------
extern "C" void kernel_launch(void* const* d_in, const int* in_sizes, int n_in,
                              void* d_out, int out_size) {
    const float* context = (const float*)d_in[0];
    const int*   target  = (const int*)  d_in[1];
    const float* embed   = (const float*)d_in[2];
    const float* W_ih    = (const float*)d_in[3];
    const float* W_hh    = (const float*)d_in[4];
    const float* b_ih    = (const float*)d_in[5];
    const float* b_hh    = (const float*)d_in[6];
    const float* out_W   = (const float*)d_in[7];
    const float* out_b   = (const float*)d_in[8];
    float* out = (float*)d_out;

    float *pGI, *pHall, *pbih, *pbhh;
    __nv_bfloat16 *pXb, *pHbf, *pWihb, *pWhhb, *pWoutb, *pLbf;
    cudaGetSymbolAddress((void**)&pXb, g_Xb);
    cudaGetSymbolAddress((void**)&pGI, g_GI);
    cudaGetSymbolAddress((void**)&pHall, g_Hall);
    cudaGetSymbolAddress((void**)&pHbf, g_Hbf);
    cudaGetSymbolAddress((void**)&pWihb, g_Wih_b);
    cudaGetSymbolAddress((void**)&pWhhb, g_Whh_b);
    cudaGetSymbolAddress((void**)&pWoutb, g_Wout_b);
    cudaGetSymbolAddress((void**)&pLbf, g_Lbf);
    cudaGetSymbolAddress((void**)&pbih, g_bih_p);
    cudaGetSymbolAddress((void**)&pbhh, g_bhh_p);

    const int SMEMBF  = 2 * (128 + 96) * 36 * 4;    // 64512 -> 3 CTAs/SM
    const int SMEMREC = 3 * (64 + 96) * 36 * 4;     // 69120
    const int SMEMSFT = Vv * 4;                      // 32000
    cudaFuncSetAttribute(bf_gemm<0>,
                         cudaFuncAttributeMaxDynamicSharedMemorySize, SMEMBF);
    cudaFuncSetAttribute(bf_gemm<1>,
                         cudaFuncAttributeMaxDynamicSharedMemorySize, SMEMBF);
    cudaFuncSetAttribute(rec_step,
                         cudaFuncAttributeMaxDynamicSharedMemorySize, SMEMREC);
    cudaFuncSetAttribute(logsoftmax_rows,
                         cudaFuncAttributeMaxDynamicSharedMemorySize, SMEMSFT);

    // prep (GI = 4th launch -> lands in the ncu capture window)
    permute_w<<<H3, 128>>>(W_ih, W_hh, b_ih, b_hh);
    gather_x<<<Tv * Bv, 64>>>(embed, target);
    conv_ctx<<<(Bv * Hv) / 1024, 256>>>(context);

    // 1) GI = X @ Wih^T + bih (bf16): (16384, 1536, K=256), grid (16, 128)
    bf_gemm<0><<<dim3(H3 / 96, (Tv * Bv) / 128), 128, SMEMBF>>>(
        pXb, pWihb, pbih, pGI, Tv * Bv, H3, H3, Ev);

    // 2) recurrence: 16 fused GEMM+gates launches (grid 16 x 16 = 256 CTAs)
    for (int t = 0; t < Tv; t++) {
        const float* hpf = (t == 0) ? context : (pHall + (size_t)(t - 1) * Bv * Hv);
        rec_step<<<dim3(H3 / 96, Bv / 64), 256, SMEMREC>>>(
            pHbf + (size_t)t * Bv * Hv, pWhhb, pGI + (size_t)t * Bv * H3, hpf,
            pHall + (size_t)t * Bv * Hv, pHbf + (size_t)(t + 1) * Bv * Hv, pbhh);
    }

    // 3) out_W -> bf16 (zero-padded to VP rows)
    conv_outw<<<(VP * Hv) / 1024, 256>>>(out_W);

    // 4) logits (bf16 in, bf16 OUT): (16384, VP, K=512), grid (84, 128);
    //    writes g_Lbf (stride VP, t*B+b row order, no remap/guard)
    bf_gemm<1><<<dim3(VP / 96, (Tv * Bv) / 128), 128, SMEMBF>>>(
        pHbf + (size_t)Bv * Hv, pWoutb, out_b, (float*)pLbf, Tv * Bv, VP, VP, Hv);

    // 5) log-softmax: bf16 logits -> fp32 logprobs with (t,b)->(b,t) remap
    logsoftmax_rows<<<Bv * Tv, 256, SMEMSFT>>>(pLbf, out);
}

// round 13
// speedup vs baseline: 1.0423x; 1.0423x over previous
#include <cuda_runtime.h>
#include <cuda_bf16.h>
#include <math.h>
#include <stdint.h>

#define Bv 1024
#define Tv 16
#define Vv 8000
#define VP 8064                    // 8064 = 84*96 (tiles exactly)
#define Ev 256
#define Hv 512
#define H3 1536

// ---------------- scratch (static device globals) ----------------------------
__device__ __nv_bfloat16 g_Xb[Tv * Bv * Ev];           // gathered inputs (bf16)
__device__ float g_GI[(size_t)Tv * Bv * H3];           // permuted input gates
__device__ float g_Hall[Tv * Bv * Hv];                 // hidden states (fp32 carry)
__device__ __nv_bfloat16 g_Hbf[(Tv + 1) * Bv * Hv];    // slice0=context, t+1=step t
__device__ __nv_bfloat16 g_Wih_b[H3 * Ev];             // permuted W_ih (bf16)
__device__ __nv_bfloat16 g_Whh_b[H3 * Hv];             // permuted W_hh (bf16)
__device__ __nv_bfloat16 g_Wout_b[VP * Hv];            // out_W (bf16, zero-padded)
__device__ float g_bih_p[H3];
__device__ float g_bhh_p[H3];

// ---------------- helpers ------------------------------------------------------
__device__ __forceinline__ uint32_t smem_u32(const void* p) {
    uint32_t a;
    asm("{ .reg .u64 t; cvta.to.shared.u64 t, %1; cvt.u32.u64 %0, t; }"
        : "=r"(a) : "l"(p));
    return a;
}
__device__ __forceinline__ uint32_t f2bf2(float lo, float hi) {
    uint32_t r;
    asm("cvt.rn.bf16x2.f32 %0, %1, %2;" : "=r"(r) : "f"(hi), "f"(lo));
    return r;
}
__device__ __forceinline__ void cp_async16(uint32_t dst, const void* src, uint32_t sz) {
    asm volatile("cp.async.cg.shared.global [%0], [%1], 16, %2;"
                 :: "r"(dst), "l"(src), "r"(sz) : "memory");
}
__device__ __forceinline__ void cp_commit() {
    asm volatile("cp.async.commit_group;" ::: "memory");
}
__device__ __forceinline__ void cp_wait1() {
    asm volatile("cp.async.wait_group 1;" ::: "memory");
}
__device__ __forceinline__ void ldm_x4(uint32_t* r, uint32_t addr) {
    asm volatile("ldmatrix.sync.aligned.m8n8.x4.shared.b16 {%0,%1,%2,%3}, [%4];"
                 : "=r"(r[0]), "=r"(r[1]), "=r"(r[2]), "=r"(r[3]) : "r"(addr));
}
__device__ __forceinline__ void ldm_x2(uint32_t* r, uint32_t addr) {
    asm volatile("ldmatrix.sync.aligned.m8n8.x2.shared.b16 {%0,%1}, [%2];"
                 : "=r"(r[0]), "=r"(r[1]) : "r"(addr));
}
__device__ __forceinline__ void mma_bf16(float* c, const uint32_t* a, const uint32_t* b) {
    asm volatile(
        "mma.sync.aligned.m16n8k16.row.col.f32.bf16.bf16.f32 "
        "{%0,%1,%2,%3}, {%4,%5,%6,%7}, {%8,%9}, {%0,%1,%2,%3};"
        : "+f"(c[0]), "+f"(c[1]), "+f"(c[2]), "+f"(c[3])
        : "r"(a[0]), "r"(a[1]), "r"(a[2]), "r"(a[3]), "r"(b[0]), "r"(b[1]));
}
__device__ __forceinline__ void stcs_f2(float* p, float x, float y) {
    asm volatile("st.global.cs.v2.f32 [%0], {%1, %2};" :: "l"(p), "f"(x), "f"(y)
                 : "memory");
}
__device__ __forceinline__ float2 ldnc_f2(const float* p) {
    float2 v;
    asm volatile("ld.global.nc.v2.f32 {%0, %1}, [%2];"
                 : "=f"(v.x), "=f"(v.y) : "l"(p));
    return v;
}
__device__ __forceinline__ float4 ldcs_f4(const float4* p) {
    float4 v;
    asm volatile("ld.global.cs.v4.f32 {%0, %1, %2, %3}, [%4];"
                 : "=f"(v.x), "=f"(v.y), "=f"(v.z), "=f"(v.w) : "l"(p));
    return v;
}
__device__ __forceinline__ void stcs_f4(float4* p, float4 v) {
    asm volatile("st.global.cs.v4.f32 [%0], {%1, %2, %3, %4};"
                 :: "l"(p), "f"(v.x), "f"(v.y), "f"(v.z), "f"(v.w) : "memory");
}
__device__ __forceinline__ float sigm(float x) { return 1.f / (1.f + expf(-x)); }

// ========== bf16 GEMM: 128 threads, BM=128, BN=96, BK=64, 2-stage ==============
// Warp grid 2x2, warp tile 64x48. 64.5 KB smem, ~168 regs -> 3 CTAs/SM.
// MODE 0: plain (GI).  MODE 1: row remap (t*B+b)->(b*T+t), store-guard at Nv.
template <int MODE>
__global__ void __launch_bounds__(128, 3)
bf_gemm(const __nv_bfloat16* __restrict__ A, const __nv_bfloat16* __restrict__ W,
        const float* __restrict__ bias, float* __restrict__ C,
        int M, int N, int Nv_, int K) {
    constexpr int BM = 128, BN = 96;
    constexpr int RSTR = 36;                 // u32 per smem row (32 data + 4 pad)
    constexpr int ASTG = BM * RSTR;
    constexpr int BSTG = BN * RSTR;
    constexpr int STG = ASTG + BSTG;         // one stage (A then B)

    extern __shared__ uint32_t smu[];
    const uint32_t sS = smem_u32(smu);       // stage0 base; stage1 at +STG*4

    const int tid = threadIdx.x;
    const int wid = tid >> 5, lane = tid & 31;
    const int grp = lane >> 2, tig = lane & 3;
    const int warpRow = wid & 1, warpCol = wid >> 1;   // 2 x 2, warp tile 64x48
    const int mBase = blockIdx.y * BM;
    const int nBase = blockIdx.x * BN;

    auto load_stage = [&](int s, int kc) {
        const int k0 = kc * 64;
        const uint32_t base = sS + s * STG * 4;
#pragma unroll
        for (int i = 0; i < 8; i++) {                   // A: 1024 x 16B
            int idx = i * 128 + tid;
            int row = idx >> 3, c = idx & 7;
            cp_async16(base + (row * RSTR + c * 4) * 4,
                       A + (size_t)(mBase + row) * K + k0 + c * 8, 16);
        }
#pragma unroll
        for (int i = 0; i < 6; i++) {                   // B: 768 x 16B (N padded)
            int idx = i * 128 + tid;
            int row = idx >> 3, c = idx & 7;
            cp_async16(base + (ASTG + row * RSTR + c * 4) * 4,
                       W + (size_t)(nBase + row) * K + k0 + c * 8, 16);
        }
    };

    const int a_r = lane & 15, a_c = (lane >> 4) * 4;
    const int b_r = (lane >> 4) * 8 + (lane & 7), b_c = ((lane >> 3) & 1) * 4;
    uint32_t aOff[4], bOff[3];
#pragma unroll
    for (int mt = 0; mt < 4; mt++)
        aOff[mt] = ((warpRow * 64 + mt * 16 + a_r) * RSTR + a_c) * 4;
#pragma unroll
    for (int nb = 0; nb < 3; nb++)
        bOff[nb] = ((ASTG + (warpCol * 48 + nb * 16 + b_r) * RSTR + b_c)) * 4;

    float acc[4][6][4];
#pragma unroll
    for (int mt = 0; mt < 4; mt++)
#pragma unroll
        for (int nt = 0; nt < 6; nt++)
#pragma unroll
            for (int j = 0; j < 4; j++) acc[mt][nt][j] = 0.f;

    const int nk = K >> 6;
    load_stage(0, 0); cp_commit();
    load_stage(1, 1); cp_commit();

    for (int k = 0; k < nk; k++) {
        cp_wait1();                          // chunk k resident
        __syncthreads();
        const uint32_t st = sS + (k & 1) * STG * 4;
#pragma unroll
        for (int kk = 0; kk < 4; kk++) {     // four k16 slices (32B apart)
            uint32_t a[4][4], b[3][4];
#pragma unroll
            for (int mt = 0; mt < 4; mt++) ldm_x4(a[mt], st + aOff[mt] + kk * 32);
#pragma unroll
            for (int nb = 0; nb < 3; nb++) ldm_x4(b[nb], st + bOff[nb] + kk * 32);
#pragma unroll
            for (int mt = 0; mt < 4; mt++)
#pragma unroll
                for (int nt = 0; nt < 6; nt++)
                    mma_bf16(acc[mt][nt], a[mt], &b[nt >> 1][(nt & 1) * 2]);
        }
        __syncthreads();                     // all reads of buf k&1 done
        if (k + 2 < nk) { load_stage(k & 1, k + 2); }
        cp_commit();                         // keep group count in lockstep
    }

    // epilogue: bias + streaming store (optional row remap; guard at true Nv)
#pragma unroll
    for (int mt = 0; mt < 4; mt++) {
        const int m0 = mBase + warpRow * 64 + mt * 16 + grp;
        const int m1 = m0 + 8;
        const int r0 = (MODE == 1) ? ((m0 & (Bv - 1)) * Tv + (m0 >> 10)) : m0;
        const int r1 = (MODE == 1) ? ((m1 & (Bv - 1)) * Tv + (m1 >> 10)) : m1;
        float* c0 = C + (size_t)r0 * Nv_;
        float* c1 = C + (size_t)r1 * Nv_;
#pragma unroll
        for (int nt = 0; nt < 6; nt++) {
            const int n = nBase + warpCol * 48 + nt * 8 + tig * 2;
            if (n < Nv_) {
                float2 bv = ldnc_f2(bias + n);
                stcs_f2(c0 + n, acc[mt][nt][0] + bv.x, acc[mt][nt][1] + bv.y);
                stcs_f2(c1 + n, acc[mt][nt][2] + bv.x, acc[mt][nt][3] + bv.y);
            }
        }
    }
}

// ================== bf16 recurrence GEMM + fused GRU gates =====================
// BM=64, BN=96 ([r32|z32|n32]), BK=64; grid (16,16) = 256 CTAs, 69 KB smem.
__global__ void __launch_bounds__(256)
rec_step(const __nv_bfloat16* __restrict__ A, const __nv_bfloat16* __restrict__ W,
         const float* __restrict__ gi, const float* __restrict__ hpf,
         float* __restrict__ hout, __nv_bfloat16* __restrict__ hbf,
         const float* __restrict__ bhh) {
    constexpr int STAGES = 3, RSTR = 36;
    constexpr int ASTG = 64 * RSTR, BSTG = 96 * RSTR;
    constexpr int K = Hv;

    extern __shared__ uint32_t smu[];
    const uint32_t sA = smem_u32(smu);
    const uint32_t sB = sA + STAGES * ASTG * 4;

    const int tid = threadIdx.x;
    const int wid = tid >> 5, lane = tid & 31;
    const int grp = lane >> 2, tig = lane & 3;
    const int warpRow = wid >> 2, warpCol = wid & 3;   // 2 x 4, warp tile 32x24
    const int mBase = blockIdx.y * 64;
    const int nBase = blockIdx.x * 96;

    auto load_stage = [&](int s, int kc) {
        const int k0 = kc * 64;
#pragma unroll
        for (int i = 0; i < 2; i++) {                   // A: 512 x 16B
            int idx = i * 256 + tid;
            int row = idx >> 3, c = idx & 7;
            cp_async16(sA + (s * ASTG + row * RSTR + c * 4) * 4,
                       A + (size_t)(mBase + row) * K + k0 + c * 8, 16);
        }
#pragma unroll
        for (int i = 0; i < 3; i++) {                   // B: 768 x 16B
            int idx = i * 256 + tid;
            int row = idx >> 3, c = idx & 7;
            cp_async16(sB + (s * BSTG + row * RSTR + c * 4) * 4,
                       W + (size_t)(nBase + row) * K + k0 + c * 8, 16);
        }
    };

    const int a_r = lane & 15, a_c = (lane >> 4) * 4;
    const int b_r = (lane >> 4) * 8 + (lane & 7), b_c = ((lane >> 3) & 1) * 4;
    const int b2_r = lane & 7, b2_c = ((lane >> 3) & 1) * 4;   // x2 (lanes 0-15)
    uint32_t aOff[2], bOff, b2Off;
#pragma unroll
    for (int mt = 0; mt < 2; mt++)
        aOff[mt] = ((warpRow * 32 + mt * 16 + a_r) * RSTR + a_c) * 4;
    bOff  = ((warpCol * 24 + b_r) * RSTR + b_c) * 4;
    b2Off = ((warpCol * 24 + 16 + b2_r) * RSTR + b2_c) * 4;

    float acc[2][3][4];
#pragma unroll
    for (int mt = 0; mt < 2; mt++)
#pragma unroll
        for (int nt = 0; nt < 3; nt++)
#pragma unroll
            for (int j = 0; j < 4; j++) acc[mt][nt][j] = 0.f;

    const int nk = K >> 6;                    // 8
    load_stage(0, 0); cp_commit();
    load_stage(1, 1); cp_commit();

    for (int k = 0; k < nk; k++) {
        const int s = k % STAGES;
        cp_wait1();
        __syncthreads();
        if (k + 2 < nk) load_stage((k + 2) % STAGES, k + 2);
        cp_commit();

        const uint32_t aS = sA + s * ASTG * 4;
        const uint32_t bS = sB + s * BSTG * 4;
#pragma unroll
        for (int kk = 0; kk < 4; kk++) {
            uint32_t a[2][4], b01[4], b2[2];
#pragma unroll
            for (int mt = 0; mt < 2; mt++) ldm_x4(a[mt], aS + aOff[mt] + kk * 32);
            ldm_x4(b01, bS + bOff + kk * 32);
            ldm_x2(b2, bS + b2Off + kk * 32);
#pragma unroll
            for (int mt = 0; mt < 2; mt++) {
                mma_bf16(acc[mt][0], a[mt], &b01[0]);
                mma_bf16(acc[mt][1], a[mt], &b01[2]);
                mma_bf16(acc[mt][2], a[mt], b2);
            }
        }
    }

    // -------- epilogue: stage GH to smem, fused gate math --------
    constexpr int GSTR = 100;
    float* gh = (float*)smu;
    asm volatile("cp.async.wait_all;" ::: "memory");
    __syncthreads();
#pragma unroll
    for (int mt = 0; mt < 2; mt++) {
        const int r0 = warpRow * 32 + mt * 16 + grp;
#pragma unroll
        for (int nt = 0; nt < 3; nt++) {
            const int n = warpCol * 24 + nt * 8 + tig * 2;
            gh[r0 * GSTR + n] = acc[mt][nt][0];
            gh[r0 * GSTR + n + 1] = acc[mt][nt][1];
            gh[(r0 + 8) * GSTR + n] = acc[mt][nt][2];
            gh[(r0 + 8) * GSTR + n + 1] = acc[mt][nt][3];
        }
    }
    __syncthreads();
    const int qBase = nBase / 3;              // nBase = bx*96 -> q base = bx*32
#pragma unroll
    for (int i = 0; i < 8; i++) {
        const int idx = i * 256 + tid;        // 0..2047
        const int row = idx >> 5;
        const int q = idx & 31;
        const int m = mBase + row;
        const float ghr = gh[row * GSTR + q] + bhh[nBase + q];
        const float ghz = gh[row * GSTR + 32 + q] + bhh[nBase + 32 + q];
        const float ghn = gh[row * GSTR + 64 + q] + bhh[nBase + 64 + q];
        const float* girow = gi + (size_t)m * H3 + nBase;
        const float r = sigm(girow[q] + ghr);
        const float z = sigm(girow[32 + q] + ghz);
        const float n = tanhf(girow[64 + q] + r * ghn);
        const int qg = qBase + q;
        const float hp = hpf[(size_t)m * Hv + qg];
        const float h = (1.f - z) * n + z * hp;
        hout[(size_t)m * Hv + qg] = h;
        hbf[(size_t)m * Hv + qg] = __float2bfloat16(h);
    }
}

// ---------------- prep kernels -------------------------------------------------
__global__ void gather_x(const float* __restrict__ embed,
                         const int* __restrict__ target) {
    int row = blockIdx.x;              // row = t*B + b
    int t = row >> 10;
    int b = row & (Bv - 1);
    int idx = (t == 0) ? 0 : target[b * Tv + (t - 1)];
    float4 v = ((const float4*)(embed + (size_t)idx * Ev))[threadIdx.x];
    uint2 o = make_uint2(f2bf2(v.x, v.y), f2bf2(v.z, v.w));
    ((uint2*)(g_Xb + (size_t)row * Ev))[threadIdx.x] = o;
}

__global__ void permute_w(const float* __restrict__ Wih, const float* __restrict__ Whh,
                          const float* __restrict__ bih, const float* __restrict__ bhh) {
    int p = blockIdx.x;                // 0..1535
    int T = p / 96, local = p - T * 96;
    int gate = local / 32, q = T * 32 + (local - gate * 32);
    int src = gate * Hv + q;
    int t = threadIdx.x;               // 128 threads
    if (t < 64) {
        float4 v = ((const float4*)(Wih + (size_t)src * Ev))[t];
        ((uint2*)(g_Wih_b + (size_t)p * Ev))[t] =
            make_uint2(f2bf2(v.x, v.y), f2bf2(v.z, v.w));
    }
    float4 w = ((const float4*)(Whh + (size_t)src * Hv))[t];
    ((uint2*)(g_Whh_b + (size_t)p * Hv))[t] =
        make_uint2(f2bf2(w.x, w.y), f2bf2(w.z, w.w));
    if (t == 0) { g_bih_p[p] = bih[src]; g_bhh_p[p] = bhh[src]; }
}

// convert out_W to bf16; zero-pad rows [Vv, VP)
__global__ void conv_outw(const float* __restrict__ W) {
    size_t i = ((size_t)blockIdx.x * 256 + threadIdx.x) * 4;   // over VP*Hv
    uint2 o = make_uint2(0u, 0u);
    if (i < (size_t)Vv * Hv) {
        float4 v = *(const float4*)(W + i);
        o = make_uint2(f2bf2(v.x, v.y), f2bf2(v.z, v.w));
    }
    *(uint2*)(g_Wout_b + i) = o;
}

__global__ void conv_ctx(const float* __restrict__ ctx) {
    size_t i = ((size_t)blockIdx.x * 256 + threadIdx.x) * 4;
    float4 v = *(const float4*)(ctx + i);
    *(uint2*)(g_Hbf + i) = make_uint2(f2bf2(v.x, v.y), f2bf2(v.z, v.w));
}

// ---------------- log-softmax, float4 path, smem row cache ---------------------
// .cs hints: the 512MB row stream is touched once each way -> keep it out of L2.
__global__ void __launch_bounds__(256)
logsoftmax_rows(float* __restrict__ out) {
    extern __shared__ float4 rowc4[];   // 2000 float4 = 8000 floats
    __shared__ float sm[256], ss[256];
    const int tid = threadIdx.x;
    float4* p4 = (float4*)(out + (size_t)blockIdx.x * Vv);

    float m = -INFINITY, s = 0.f;
    for (int i = tid; i < Vv / 4; i += 256) {
        float4 x = ldcs_f4(p4 + i);
        rowc4[i] = x;
        float mx = fmaxf(fmaxf(x.x, x.y), fmaxf(x.z, x.w));
        if (mx > m) {
            s = s * expf(m - mx);
            m = mx;
        }
        s += expf(x.x - m) + expf(x.y - m) + expf(x.z - m) + expf(x.w - m);
    }
    sm[tid] = m; ss[tid] = s;
    __syncthreads();
    for (int st = 128; st > 0; st >>= 1) {
        if (tid < st) {
            float m2 = sm[tid + st], s2 = ss[tid + st];
            float M = fmaxf(sm[tid], m2);
            ss[tid] = ss[tid] * expf(sm[tid] - M) + s2 * expf(m2 - M);
            sm[tid] = M;
        }
        __syncthreads();
    }
    const float lse = sm[0] + logf(ss[0]);
    for (int i = tid; i < Vv / 4; i += 256) {
        float4 x = rowc4[i];
        stcs_f4(p4 + i, make_float4(x.x - lse, x.y - lse, x.z - lse, x.w - lse));
    }
}

// ---------------- launch --------------------------------------------------------
extern "C" void kernel_launch(void* const* d_in, const int* in_sizes, int n_in,
                              void* d_out, int out_size) {
    const float* context = (const float*)d_in[0];
    const int*   target  = (const int*)  d_in[1];
    const float* embed   = (const float*)d_in[2];
    const float* W_ih    = (const float*)d_in[3];
    const float* W_hh    = (const float*)d_in[4];
    const float* b_ih    = (const float*)d_in[5];
    const float* b_hh    = (const float*)d_in[6];
    const float* out_W   = (const float*)d_in[7];
    const float* out_b   = (const float*)d_in[8];
    float* out = (float*)d_out;

    float *pGI, *pHall, *pbih, *pbhh;
    __nv_bfloat16 *pXb, *pHbf, *pWihb, *pWhhb, *pWoutb;
    cudaGetSymbolAddress((void**)&pXb, g_Xb);
    cudaGetSymbolAddress((void**)&pGI, g_GI);
    cudaGetSymbolAddress((void**)&pHall, g_Hall);
    cudaGetSymbolAddress((void**)&pHbf, g_Hbf);
    cudaGetSymbolAddress((void**)&pWihb, g_Wih_b);
    cudaGetSymbolAddress((void**)&pWhhb, g_Whh_b);
    cudaGetSymbolAddress((void**)&pWoutb, g_Wout_b);
    cudaGetSymbolAddress((void**)&pbih, g_bih_p);
    cudaGetSymbolAddress((void**)&pbhh, g_bhh_p);

    const int SMEMBF  = 2 * (128 + 96) * 36 * 4;    // 64512 -> 3 CTAs/SM
    const int SMEMREC = 3 * (64 + 96) * 36 * 4;     // 69120
    const int SMEMSFT = Vv * 4;                      // 32000
    cudaFuncSetAttribute(bf_gemm<0>,
                         cudaFuncAttributeMaxDynamicSharedMemorySize, SMEMBF);
    cudaFuncSetAttribute(bf_gemm<1>,
                         cudaFuncAttributeMaxDynamicSharedMemorySize, SMEMBF);
    cudaFuncSetAttribute(rec_step,
                         cudaFuncAttributeMaxDynamicSharedMemorySize, SMEMREC);
    cudaFuncSetAttribute(logsoftmax_rows,
                         cudaFuncAttributeMaxDynamicSharedMemorySize, SMEMSFT);

    // prep (GI = 4th launch -> lands in the ncu capture window)
    permute_w<<<H3, 128>>>(W_ih, W_hh, b_ih, b_hh);
    gather_x<<<Tv * Bv, 64>>>(embed, target);
    conv_ctx<<<(Bv * Hv) / 1024, 256>>>(context);

    // 1) GI = X @ Wih^T + bih (bf16): (16384, 1536, K=256), grid (16, 128)
    bf_gemm<0><<<dim3(H3 / 96, (Tv * Bv) / 128), 128, SMEMBF>>>(
        pXb, pWihb, pbih, pGI, Tv * Bv, H3, H3, Ev);

    // 2) recurrence: 16 fused GEMM+gates launches (grid 16 x 16 = 256 CTAs)
    for (int t = 0; t < Tv; t++) {
        const float* hpf = (t == 0) ? context : (pHall + (size_t)(t - 1) * Bv * Hv);
        rec_step<<<dim3(H3 / 96, Bv / 64), 256, SMEMREC>>>(
            pHbf + (size_t)t * Bv * Hv, pWhhb, pGI + (size_t)t * Bv * H3, hpf,
            pHall + (size_t)t * Bv * Hv, pHbf + (size_t)(t + 1) * Bv * Hv, pbhh);
    }

    // 3) out_W -> bf16 (zero-padded to VP rows)
    conv_outw<<<(VP * Hv) / 1024, 256>>>(out_W);

    // 4) logits (bf16): (16384, VP, K=512), grid (84, 128), remapped rows
    bf_gemm<1><<<dim3(VP / 96, (Tv * Bv) / 128), 128, SMEMBF>>>(
        pHbf + (size_t)Bv * Hv, pWoutb, out_b, out, Tv * Bv, VP, Vv, Hv);

    // 5) in-place log-softmax per (b,t) row
    logsoftmax_rows<<<Bv * Tv, 256, SMEMSFT>>>(out);
}

// round 15
// speedup vs baseline: 1.1318x; 1.0859x over previous
#include <cuda_runtime.h>
#include <cuda_bf16.h>
#include <math.h>
#include <stdint.h>

#define Bv 1024
#define Tv 16
#define Vv 8000
#define VP 8064                    // 8064 = 84*96 (tiles exactly)
#define Ev 256
#define Hv 512
#define H3 1536

// ---------------- scratch (static device globals) ----------------------------
__device__ __nv_bfloat16 g_Xb[Tv * Bv * Ev];           // gathered inputs (bf16)
__device__ float g_GI[(size_t)Tv * Bv * H3];           // permuted input gates
__device__ float g_Hall[Tv * Bv * Hv];                 // hidden states (fp32 carry)
__device__ __nv_bfloat16 g_Hbf[(Tv + 1) * Bv * Hv];    // slice0=context, t+1=step t
__device__ __nv_bfloat16 g_Wih_b[H3 * Ev];             // permuted W_ih (bf16)
__device__ __nv_bfloat16 g_Whh_b[H3 * Hv];             // permuted W_hh (bf16)
__device__ __nv_bfloat16 g_Wout_b[VP * Hv];            // out_W (bf16, zero-padded)
__device__ __nv_bfloat16 g_Lbf[(size_t)Tv * Bv * VP];  // bf16 logits (t*B+b rows)
__device__ float g_bih_p[H3];
__device__ float g_bhh_p[H3];
__device__ float g_bout_p[VP];                          // out_b zero-padded

// ---------------- helpers ------------------------------------------------------
__device__ __forceinline__ uint32_t smem_u32(const void* p) {
    uint32_t a;
    asm("{ .reg .u64 t; cvta.to.shared.u64 t, %1; cvt.u32.u64 %0, t; }"
        : "=r"(a) : "l"(p));
    return a;
}
__device__ __forceinline__ uint32_t f2bf2(float lo, float hi) {
    uint32_t r;
    asm("cvt.rn.bf16x2.f32 %0, %1, %2;" : "=r"(r) : "f"(hi), "f"(lo));
    return r;
}
__device__ __forceinline__ void cp_async16(uint32_t dst, const void* src, uint32_t sz) {
    asm volatile("cp.async.cg.shared.global [%0], [%1], 16, %2;"
                 :: "r"(dst), "l"(src), "r"(sz) : "memory");
}
__device__ __forceinline__ void cp_commit() {
    asm volatile("cp.async.commit_group;" ::: "memory");
}
__device__ __forceinline__ void cp_wait1() {
    asm volatile("cp.async.wait_group 1;" ::: "memory");
}
__device__ __forceinline__ void ldm_x4(uint32_t* r, uint32_t addr) {
    asm volatile("ldmatrix.sync.aligned.m8n8.x4.shared.b16 {%0,%1,%2,%3}, [%4];"
                 : "=r"(r[0]), "=r"(r[1]), "=r"(r[2]), "=r"(r[3]) : "r"(addr));
}
__device__ __forceinline__ void ldm_x2(uint32_t* r, uint32_t addr) {
    asm volatile("ldmatrix.sync.aligned.m8n8.x2.shared.b16 {%0,%1}, [%2];"
                 : "=r"(r[0]), "=r"(r[1]) : "r"(addr));
}
__device__ __forceinline__ void mma_bf16(float* c, const uint32_t* a, const uint32_t* b) {
    asm volatile(
        "mma.sync.aligned.m16n8k16.row.col.f32.bf16.bf16.f32 "
        "{%0,%1,%2,%3}, {%4,%5,%6,%7}, {%8,%9}, {%0,%1,%2,%3};"
        : "+f"(c[0]), "+f"(c[1]), "+f"(c[2]), "+f"(c[3])
        : "r"(a[0]), "r"(a[1]), "r"(a[2]), "r"(a[3]), "r"(b[0]), "r"(b[1]));
}
__device__ __forceinline__ void stcs_f2(float* p, float x, float y) {
    asm volatile("st.global.cs.v2.f32 [%0], {%1, %2};" :: "l"(p), "f"(x), "f"(y)
                 : "memory");
}
__device__ __forceinline__ float2 ldnc_f2(const float* p) {
    float2 v;
    asm volatile("ld.global.nc.v2.f32 {%0, %1}, [%2];"
                 : "=f"(v.x), "=f"(v.y) : "l"(p));
    return v;
}
__device__ __forceinline__ uint4 ldcs_u4(const uint4* p) {
    uint4 v;
    asm volatile("ld.global.cs.v4.u32 {%0, %1, %2, %3}, [%4];"
                 : "=r"(v.x), "=r"(v.y), "=r"(v.z), "=r"(v.w) : "l"(p));
    return v;
}
__device__ __forceinline__ void stcs_u4(uint4* p, uint4 v) {
    asm volatile("st.global.cs.v4.u32 [%0], {%1, %2, %3, %4};"
                 :: "l"(p), "r"(v.x), "r"(v.y), "r"(v.z), "r"(v.w) : "memory");
}
__device__ __forceinline__ void stcs_f4(float4* p, float4 v) {
    asm volatile("st.global.cs.v4.f32 [%0], {%1, %2, %3, %4};"
                 :: "l"(p), "f"(v.x), "f"(v.y), "f"(v.z), "f"(v.w) : "memory");
}
__device__ __forceinline__ float sigm(float x) { return 1.f / (1.f + expf(-x)); }

// ========== bf16 GEMM: 128 threads, BM=128, BN=96, BK=64, 2-stage ==============
// Warp grid 2x2, warp tile 64x48. 64.5 KB smem, ~168 regs -> 3 CTAs/SM.
// MODE 0: fp32 out + bias, stride Nv_ (GI).
// MODE 1: bf16 out via smem-staged coalesced uint4 stores, stride VP (logits).
template <int MODE>
__global__ void __launch_bounds__(128, 3)
bf_gemm(const __nv_bfloat16* __restrict__ A, const __nv_bfloat16* __restrict__ W,
        const float* __restrict__ bias, float* __restrict__ C,
        int M, int N, int Nv_, int K) {
    constexpr int BM = 128, BN = 96;
    constexpr int RSTR = 36;                 // u32 per smem row (32 data + 4 pad)
    constexpr int ASTG = BM * RSTR;
    constexpr int BSTG = BN * RSTR;
    constexpr int STG = ASTG + BSTG;         // one stage (A then B)

    extern __shared__ uint32_t smu[];
    const uint32_t sS = smem_u32(smu);       // stage0 base; stage1 at +STG*4

    const int tid = threadIdx.x;
    const int wid = tid >> 5, lane = tid & 31;
    const int grp = lane >> 2, tig = lane & 3;
    const int warpRow = wid & 1, warpCol = wid >> 1;   // 2 x 2, warp tile 64x48
    const int mBase = blockIdx.y * BM;
    const int nBase = blockIdx.x * BN;

    auto load_stage = [&](int s, int kc) {
        const int k0 = kc * 64;
        const uint32_t base = sS + s * STG * 4;
#pragma unroll
        for (int i = 0; i < 8; i++) {                   // A: 1024 x 16B
            int idx = i * 128 + tid;
            int row = idx >> 3, c = idx & 7;
            cp_async16(base + (row * RSTR + c * 4) * 4,
                       A + (size_t)(mBase + row) * K + k0 + c * 8, 16);
        }
#pragma unroll
        for (int i = 0; i < 6; i++) {                   // B: 768 x 16B (N padded)
            int idx = i * 128 + tid;
            int row = idx >> 3, c = idx & 7;
            cp_async16(base + (ASTG + row * RSTR + c * 4) * 4,
                       W + (size_t)(nBase + row) * K + k0 + c * 8, 16);
        }
    };

    const int a_r = lane & 15, a_c = (lane >> 4) * 4;
    const int b_r = (lane >> 4) * 8 + (lane & 7), b_c = ((lane >> 3) & 1) * 4;
    uint32_t aOff[4], bOff[3];
#pragma unroll
    for (int mt = 0; mt < 4; mt++)
        aOff[mt] = ((warpRow * 64 + mt * 16 + a_r) * RSTR + a_c) * 4;
#pragma unroll
    for (int nb = 0; nb < 3; nb++)
        bOff[nb] = ((ASTG + (warpCol * 48 + nb * 16 + b_r) * RSTR + b_c)) * 4;

    float acc[4][6][4];
#pragma unroll
    for (int mt = 0; mt < 4; mt++)
#pragma unroll
        for (int nt = 0; nt < 6; nt++)
#pragma unroll
            for (int j = 0; j < 4; j++) acc[mt][nt][j] = 0.f;

    const int nk = K >> 6;
    load_stage(0, 0); cp_commit();
    load_stage(1, 1); cp_commit();

    for (int k = 0; k < nk; k++) {
        cp_wait1();                          // chunk k resident
        __syncthreads();
        const uint32_t st = sS + (k & 1) * STG * 4;
#pragma unroll
        for (int kk = 0; kk < 4; kk++) {     // four k16 slices (32B apart)
            uint32_t a[4][4], b[3][4];
#pragma unroll
            for (int mt = 0; mt < 4; mt++) ldm_x4(a[mt], st + aOff[mt] + kk * 32);
#pragma unroll
            for (int nb = 0; nb < 3; nb++) ldm_x4(b[nb], st + bOff[nb] + kk * 32);
#pragma unroll
            for (int mt = 0; mt < 4; mt++)
#pragma unroll
                for (int nt = 0; nt < 6; nt++)
                    mma_bf16(acc[mt][nt], a[mt], &b[nt >> 1][(nt & 1) * 2]);
        }
        __syncthreads();                     // all reads of buf k&1 done
        if (k + 2 < nk) { load_stage(k & 1, k + 2); }
        cp_commit();                         // keep group count in lockstep
    }

    // ---------------- epilogue ----------------
    if constexpr (MODE == 0) {               // fp32 + bias, stride Nv_
#pragma unroll
        for (int mt = 0; mt < 4; mt++) {
            const int m0 = mBase + warpRow * 64 + mt * 16 + grp;
            const int m1 = m0 + 8;
            float* c0 = C + (size_t)m0 * Nv_;
            float* c1 = C + (size_t)m1 * Nv_;
#pragma unroll
            for (int nt = 0; nt < 6; nt++) {
                const int n = nBase + warpCol * 48 + nt * 8 + tig * 2;
                float2 bv = ldnc_f2(bias + n);
                stcs_f2(c0 + n, acc[mt][nt][0] + bv.x, acc[mt][nt][1] + bv.y);
                stcs_f2(c1 + n, acc[mt][nt][2] + bv.x, acc[mt][nt][3] + bv.y);
            }
        }
    } else {
        // bf16 tile staged in smem, then coalesced 16B stores (stride VP)
        constexpr int OSTR = 104;            // bf16 per row (208 B, 16B-aligned)
        __nv_bfloat16* ot = (__nv_bfloat16*)smu;
        __syncthreads();                     // mainloop smem free
#pragma unroll
        for (int mt = 0; mt < 4; mt++) {
            const int r0 = warpRow * 64 + mt * 16 + grp;
            const int r1 = r0 + 8;
#pragma unroll
            for (int nt = 0; nt < 6; nt++) {
                const int n = warpCol * 48 + nt * 8 + tig * 2;
                float2 bv = ldnc_f2(bias + nBase + n);
                *(uint32_t*)(ot + r0 * OSTR + n) =
                    f2bf2(acc[mt][nt][0] + bv.x, acc[mt][nt][1] + bv.y);
                *(uint32_t*)(ot + r1 * OSTR + n) =
                    f2bf2(acc[mt][nt][2] + bv.x, acc[mt][nt][3] + bv.y);
            }
        }
        __syncthreads();
        __nv_bfloat16* Cb = (__nv_bfloat16*)C;
#pragma unroll
        for (int i = 0; i < 12; i++) {       // 1536 uint4 = 128 rows x 12 chunks
            int idx = i * 128 + tid;
            int row = idx / 12, c = idx - row * 12;
            uint4 v = *(const uint4*)(ot + row * OSTR + c * 8);
            stcs_u4((uint4*)(Cb + (size_t)(mBase + row) * VP + nBase) + c, v);
        }
    }
}

// ================== bf16 recurrence GEMM + fused GRU gates =====================
// BM=64, BN=96 ([r32|z32|n32]), BK=64; grid (16,16) = 256 CTAs, 69 KB smem.
__global__ void __launch_bounds__(256)
rec_step(const __nv_bfloat16* __restrict__ A, const __nv_bfloat16* __restrict__ W,
         const float* __restrict__ gi, const float* __restrict__ hpf,
         float* __restrict__ hout, __nv_bfloat16* __restrict__ hbf,
         const float* __restrict__ bhh) {
    constexpr int STAGES = 3, RSTR = 36;
    constexpr int ASTG = 64 * RSTR, BSTG = 96 * RSTR;
    constexpr int K = Hv;

    extern __shared__ uint32_t smu[];
    const uint32_t sA = smem_u32(smu);
    const uint32_t sB = sA + STAGES * ASTG * 4;

    const int tid = threadIdx.x;
    const int wid = tid >> 5, lane = tid & 31;
    const int grp = lane >> 2, tig = lane & 3;
    const int warpRow = wid >> 2, warpCol = wid & 3;   // 2 x 4, warp tile 32x24
    const int mBase = blockIdx.y * 64;
    const int nBase = blockIdx.x * 96;

    auto load_stage = [&](int s, int kc) {
        const int k0 = kc * 64;
#pragma unroll
        for (int i = 0; i < 2; i++) {                   // A: 512 x 16B
            int idx = i * 256 + tid;
            int row = idx >> 3, c = idx & 7;
            cp_async16(sA + (s * ASTG + row * RSTR + c * 4) * 4,
                       A + (size_t)(mBase + row) * K + k0 + c * 8, 16);
        }
#pragma unroll
        for (int i = 0; i < 3; i++) {                   // B: 768 x 16B
            int idx = i * 256 + tid;
            int row = idx >> 3, c = idx & 7;
            cp_async16(sB + (s * BSTG + row * RSTR + c * 4) * 4,
                       W + (size_t)(nBase + row) * K + k0 + c * 8, 16);
        }
    };

    const int a_r = lane & 15, a_c = (lane >> 4) * 4;
    const int b_r = (lane >> 4) * 8 + (lane & 7), b_c = ((lane >> 3) & 1) * 4;
    const int b2_r = lane & 7, b2_c = ((lane >> 3) & 1) * 4;   // x2 (lanes 0-15)
    uint32_t aOff[2], bOff, b2Off;
#pragma unroll
    for (int mt = 0; mt < 2; mt++)
        aOff[mt] = ((warpRow * 32 + mt * 16 + a_r) * RSTR + a_c) * 4;
    bOff  = ((warpCol * 24 + b_r) * RSTR + b_c) * 4;
    b2Off = ((warpCol * 24 + 16 + b2_r) * RSTR + b2_c) * 4;

    float acc[2][3][4];
#pragma unroll
    for (int mt = 0; mt < 2; mt++)
#pragma unroll
        for (int nt = 0; nt < 3; nt++)
#pragma unroll
            for (int j = 0; j < 4; j++) acc[mt][nt][j] = 0.f;

    const int nk = K >> 6;                    // 8
    load_stage(0, 0); cp_commit();
    load_stage(1, 1); cp_commit();

    for (int k = 0; k < nk; k++) {
        const int s = k % STAGES;
        cp_wait1();
        __syncthreads();
        if (k + 2 < nk) load_stage((k + 2) % STAGES, k + 2);
        cp_commit();

        const uint32_t aS = sA + s * ASTG * 4;
        const uint32_t bS = sB + s * BSTG * 4;
#pragma unroll
        for (int kk = 0; kk < 4; kk++) {
            uint32_t a[2][4], b01[4], b2[2];
#pragma unroll
            for (int mt = 0; mt < 2; mt++) ldm_x4(a[mt], aS + aOff[mt] + kk * 32);
            ldm_x4(b01, bS + bOff + kk * 32);
            ldm_x2(b2, bS + b2Off + kk * 32);
#pragma unroll
            for (int mt = 0; mt < 2; mt++) {
                mma_bf16(acc[mt][0], a[mt], &b01[0]);
                mma_bf16(acc[mt][1], a[mt], &b01[2]);
                mma_bf16(acc[mt][2], a[mt], b2);
            }
        }
    }

    // -------- epilogue: stage GH to smem, fused gate math --------
    constexpr int GSTR = 100;
    float* gh = (float*)smu;
    asm volatile("cp.async.wait_all;" ::: "memory");
    __syncthreads();
#pragma unroll
    for (int mt = 0; mt < 2; mt++) {
        const int r0 = warpRow * 32 + mt * 16 + grp;
#pragma unroll
        for (int nt = 0; nt < 3; nt++) {
            const int n = warpCol * 24 + nt * 8 + tig * 2;
            gh[r0 * GSTR + n] = acc[mt][nt][0];
            gh[r0 * GSTR + n + 1] = acc[mt][nt][1];
            gh[(r0 + 8) * GSTR + n] = acc[mt][nt][2];
            gh[(r0 + 8) * GSTR + n + 1] = acc[mt][nt][3];
        }
    }
    __syncthreads();
    const int qBase = nBase / 3;              // nBase = bx*96 -> q base = bx*32
#pragma unroll
    for (int i = 0; i < 8; i++) {
        const int idx = i * 256 + tid;        // 0..2047
        const int row = idx >> 5;
        const int q = idx & 31;
        const int m = mBase + row;
        const float ghr = gh[row * GSTR + q] + bhh[nBase + q];
        const float ghz = gh[row * GSTR + 32 + q] + bhh[nBase + 32 + q];
        const float ghn = gh[row * GSTR + 64 + q] + bhh[nBase + 64 + q];
        const float* girow = gi + (size_t)m * H3 + nBase;
        const float r = sigm(girow[q] + ghr);
        const float z = sigm(girow[32 + q] + ghz);
        const float n = tanhf(girow[64 + q] + r * ghn);
        const int qg = qBase + q;
        const float hp = hpf[(size_t)m * Hv + qg];
        const float h = (1.f - z) * n + z * hp;
        hout[(size_t)m * Hv + qg] = h;
        hbf[(size_t)m * Hv + qg] = __float2bfloat16(h);
    }
}

// ---------------- prep kernels -------------------------------------------------
__global__ void gather_x(const float* __restrict__ embed,
                         const int* __restrict__ target) {
    int row = blockIdx.x;              // row = t*B + b
    int t = row >> 10;
    int b = row & (Bv - 1);
    int idx = (t == 0) ? 0 : target[b * Tv + (t - 1)];
    float4 v = ((const float4*)(embed + (size_t)idx * Ev))[threadIdx.x];
    uint2 o = make_uint2(f2bf2(v.x, v.y), f2bf2(v.z, v.w));
    ((uint2*)(g_Xb + (size_t)row * Ev))[threadIdx.x] = o;
}

__global__ void permute_w(const float* __restrict__ Wih, const float* __restrict__ Whh,
                          const float* __restrict__ bih, const float* __restrict__ bhh) {
    int p = blockIdx.x;                // 0..1535
    int T = p / 96, local = p - T * 96;
    int gate = local / 32, q = T * 32 + (local - gate * 32);
    int src = gate * Hv + q;
    int t = threadIdx.x;               // 128 threads
    if (t < 64) {
        float4 v = ((const float4*)(Wih + (size_t)src * Ev))[t];
        ((uint2*)(g_Wih_b + (size_t)p * Ev))[t] =
            make_uint2(f2bf2(v.x, v.y), f2bf2(v.z, v.w));
    }
    float4 w = ((const float4*)(Whh + (size_t)src * Hv))[t];
    ((uint2*)(g_Whh_b + (size_t)p * Hv))[t] =
        make_uint2(f2bf2(w.x, w.y), f2bf2(w.z, w.w));
    if (t == 0) { g_bih_p[p] = bih[src]; g_bhh_p[p] = bhh[src]; }
}

// convert out_W to bf16; zero-pad rows [Vv, VP)
__global__ void conv_outw(const float* __restrict__ W) {
    size_t i = ((size_t)blockIdx.x * 256 + threadIdx.x) * 4;   // over VP*Hv
    uint2 o = make_uint2(0u, 0u);
    if (i < (size_t)Vv * Hv) {
        float4 v = *(const float4*)(W + i);
        o = make_uint2(f2bf2(v.x, v.y), f2bf2(v.z, v.w));
    }
    *(uint2*)(g_Wout_b + i) = o;
}

__global__ void pad_bias(const float* __restrict__ b) {
    int i = blockIdx.x * 256 + threadIdx.x;
    if (i < VP) g_bout_p[i] = (i < Vv) ? b[i] : 0.f;
}

__global__ void conv_ctx(const float* __restrict__ ctx) {
    size_t i = ((size_t)blockIdx.x * 256 + threadIdx.x) * 4;
    float4 v = *(const float4*)(ctx + i);
    *(uint2*)(g_Hbf + i) = make_uint2(f2bf2(v.x, v.y), f2bf2(v.z, v.w));
}

// -------- log-softmax: bf16 logits (t*B+b rows) -> fp32 logprobs (b*T+t) -------
__global__ void __launch_bounds__(256)
logsoftmax_rows(const __nv_bfloat16* __restrict__ Lbf, float* __restrict__ out) {
    extern __shared__ float rowc[];     // 8000 floats
    __shared__ float sm[256], ss[256];
    const int tid = threadIdx.x;
    const int ro = blockIdx.x;          // output row (b*T + t)
    const int b = ro >> 4, t = ro & 15;
    const uint4* src = (const uint4*)(Lbf + (size_t)(t * Bv + b) * VP);

    float m = -INFINITY, s = 0.f;
    for (int i = tid; i < Vv / 8; i += 256) {      // 1000 x 16B loads
        uint4 u = ldcs_u4(src + i);
        float v[8];
        v[0] = __uint_as_float(u.x << 16); v[1] = __uint_as_float(u.x & 0xffff0000u);
        v[2] = __uint_as_float(u.y << 16); v[3] = __uint_as_float(u.y & 0xffff0000u);
        v[4] = __uint_as_float(u.z << 16); v[5] = __uint_as_float(u.z & 0xffff0000u);
        v[6] = __uint_as_float(u.w << 16); v[7] = __uint_as_float(u.w & 0xffff0000u);
        float mx = v[0];
#pragma unroll
        for (int j = 1; j < 8; j++) mx = fmaxf(mx, v[j]);
        if (mx > m) { s *= expf(m - mx); m = mx; }
#pragma unroll
        for (int j = 0; j < 8; j++) {
            rowc[8 * i + j] = v[j];
            s += expf(v[j] - m);
        }
    }
    sm[tid] = m; ss[tid] = s;
    __syncthreads();
    for (int st = 128; st > 0; st >>= 1) {
        if (tid < st) {
            float m2 = sm[tid + st], s2 = ss[tid + st];
            float M = fmaxf(sm[tid], m2);
            ss[tid] = ss[tid] * expf(sm[tid] - M) + s2 * expf(m2 - M);
            sm[tid] = M;
        }
        __syncthreads();
    }
    const float lse = sm[0] + logf(ss[0]);
    float4* dst = (float4*)(out + (size_t)ro * Vv);
    for (int i = tid; i < Vv / 4; i += 256) {
        float4 x = ((const float4*)rowc)[i];
        stcs_f4(dst + i, make_float4(x.x - lse, x.y - lse, x.z - lse, x.w - lse));
    }
}

// ---------------- launch --------------------------------------------------------
extern "C" void kernel_launch(void* const* d_in, const int* in_sizes, int n_in,
                              void* d_out, int out_size) {
    const float* context = (const float*)d_in[0];
    const int*   target  = (const int*)  d_in[1];
    const float* embed   = (const float*)d_in[2];
    const float* W_ih    = (const float*)d_in[3];
    const float* W_hh    = (const float*)d_in[4];
    const float* b_ih    = (const float*)d_in[5];
    const float* b_hh    = (const float*)d_in[6];
    const float* out_W   = (const float*)d_in[7];
    const float* out_b   = (const float*)d_in[8];
    float* out = (float*)d_out;

    float *pGI, *pHall, *pbih, *pbhh, *pbout;
    __nv_bfloat16 *pXb, *pHbf, *pWihb, *pWhhb, *pWoutb, *pLbf;
    cudaGetSymbolAddress((void**)&pXb, g_Xb);
    cudaGetSymbolAddress((void**)&pGI, g_GI);
    cudaGetSymbolAddress((void**)&pHall, g_Hall);
    cudaGetSymbolAddress((void**)&pHbf, g_Hbf);
    cudaGetSymbolAddress((void**)&pWihb, g_Wih_b);
    cudaGetSymbolAddress((void**)&pWhhb, g_Whh_b);
    cudaGetSymbolAddress((void**)&pWoutb, g_Wout_b);
    cudaGetSymbolAddress((void**)&pLbf, g_Lbf);
    cudaGetSymbolAddress((void**)&pbih, g_bih_p);
    cudaGetSymbolAddress((void**)&pbhh, g_bhh_p);
    cudaGetSymbolAddress((void**)&pbout, g_bout_p);

    const int SMEMBF  = 2 * (128 + 96) * 36 * 4;    // 64512 -> 3 CTAs/SM
    const int SMEMREC = 3 * (64 + 96) * 36 * 4;     // 69120
    const int SMEMSFT = Vv * 4;                      // 32000
    cudaFuncSetAttribute(bf_gemm<0>,
                         cudaFuncAttributeMaxDynamicSharedMemorySize, SMEMBF);
    cudaFuncSetAttribute(bf_gemm<1>,
                         cudaFuncAttributeMaxDynamicSharedMemorySize, SMEMBF);
    cudaFuncSetAttribute(rec_step,
                         cudaFuncAttributeMaxDynamicSharedMemorySize, SMEMREC);
    cudaFuncSetAttribute(logsoftmax_rows,
                         cudaFuncAttributeMaxDynamicSharedMemorySize, SMEMSFT);

    // prep (GI = 4th launch -> lands in the ncu capture window)
    permute_w<<<H3, 128>>>(W_ih, W_hh, b_ih, b_hh);
    gather_x<<<Tv * Bv, 64>>>(embed, target);
    conv_ctx<<<(Bv * Hv) / 1024, 256>>>(context);

    // 1) GI = X @ Wih^T + bih (bf16): (16384, 1536, K=256), grid (16, 128)
    bf_gemm<0><<<dim3(H3 / 96, (Tv * Bv) / 128), 128, SMEMBF>>>(
        pXb, pWihb, pbih, pGI, Tv * Bv, H3, H3, Ev);

    // 2) recurrence: 16 fused GEMM+gates launches (grid 16 x 16 = 256 CTAs)
    for (int t = 0; t < Tv; t++) {
        const float* hpf = (t == 0) ? context : (pHall + (size_t)(t - 1) * Bv * Hv);
        rec_step<<<dim3(H3 / 96, Bv / 64), 256, SMEMREC>>>(
            pHbf + (size_t)t * Bv * Hv, pWhhb, pGI + (size_t)t * Bv * H3, hpf,
            pHall + (size_t)t * Bv * Hv, pHbf + (size_t)(t + 1) * Bv * Hv, pbhh);
    }

    // 3) out_W -> bf16 (zero-padded to VP rows); padded out_b
    conv_outw<<<(VP * Hv) / 1024, 256>>>(out_W);
    pad_bias<<<(VP + 255) / 256, 256>>>(out_b);

    // 4) logits (bf16 in, bf16 OUT staged via smem): grid (84, 128)
    bf_gemm<1><<<dim3(VP / 96, (Tv * Bv) / 128), 128, SMEMBF>>>(
        pHbf + (size_t)Bv * Hv, pWoutb, pbout, (float*)pLbf, Tv * Bv, VP, VP, Hv);

    // 5) log-softmax: bf16 logits -> fp32 logprobs with (t,b)->(b,t) remap
    logsoftmax_rows<<<Bv * Tv, 256, SMEMSFT>>>(pLbf, out);
}

// round 16
// speedup vs baseline: 1.1703x; 1.0340x over previous
#include <cuda_runtime.h>
#include <cuda_bf16.h>
#include <math.h>
#include <stdint.h>

#define Bv 1024
#define Tv 16
#define Vv 8000
#define VP 8064                    // 8064 = 84*96 (tiles exactly)
#define Ev 256
#define Hv 512
#define H3 1536

// ---------------- scratch (static device globals) ----------------------------
__device__ __nv_bfloat16 g_Xb[Tv * Bv * Ev];           // gathered inputs (bf16)
__device__ __nv_bfloat16 g_GIb[(size_t)Tv * Bv * H3];  // input gates (bf16) 48 MB
__device__ float g_Hall[Tv * Bv * Hv];                 // hidden states (fp32 carry)
__device__ __nv_bfloat16 g_Hbf[(Tv + 1) * Bv * Hv];    // slice0=context, t+1=step t
__device__ __nv_bfloat16 g_Wih_b[H3 * Ev];             // permuted W_ih (bf16)
__device__ __nv_bfloat16 g_Whh_b[H3 * Hv];             // permuted W_hh (bf16)
__device__ __nv_bfloat16 g_Wout_b[VP * Hv];            // out_W (bf16, zero-padded)
__device__ __nv_bfloat16 g_Lbf[(size_t)Tv * Bv * VP];  // bf16 logits (t*B+b rows)
__device__ float g_bih_p[H3];
__device__ float g_bhh_p[H3];
__device__ float g_bout_p[VP];                          // out_b zero-padded

// ---------------- helpers ------------------------------------------------------
__device__ __forceinline__ uint32_t smem_u32(const void* p) {
    uint32_t a;
    asm("{ .reg .u64 t; cvta.to.shared.u64 t, %1; cvt.u32.u64 %0, t; }"
        : "=r"(a) : "l"(p));
    return a;
}
__device__ __forceinline__ uint32_t f2bf2(float lo, float hi) {
    uint32_t r;
    asm("cvt.rn.bf16x2.f32 %0, %1, %2;" : "=r"(r) : "f"(hi), "f"(lo));
    return r;
}
__device__ __forceinline__ void cp_async16(uint32_t dst, const void* src, uint32_t sz) {
    asm volatile("cp.async.cg.shared.global [%0], [%1], 16, %2;"
                 :: "r"(dst), "l"(src), "r"(sz) : "memory");
}
__device__ __forceinline__ void cp_commit() {
    asm volatile("cp.async.commit_group;" ::: "memory");
}
__device__ __forceinline__ void cp_wait1() {
    asm volatile("cp.async.wait_group 1;" ::: "memory");
}
__device__ __forceinline__ void ldm_x4(uint32_t* r, uint32_t addr) {
    asm volatile("ldmatrix.sync.aligned.m8n8.x4.shared.b16 {%0,%1,%2,%3}, [%4];"
                 : "=r"(r[0]), "=r"(r[1]), "=r"(r[2]), "=r"(r[3]) : "r"(addr));
}
__device__ __forceinline__ void ldm_x2(uint32_t* r, uint32_t addr) {
    asm volatile("ldmatrix.sync.aligned.m8n8.x2.shared.b16 {%0,%1}, [%2];"
                 : "=r"(r[0]), "=r"(r[1]) : "r"(addr));
}
__device__ __forceinline__ void mma_bf16(float* c, const uint32_t* a, const uint32_t* b) {
    asm volatile(
        "mma.sync.aligned.m16n8k16.row.col.f32.bf16.bf16.f32 "
        "{%0,%1,%2,%3}, {%4,%5,%6,%7}, {%8,%9}, {%0,%1,%2,%3};"
        : "+f"(c[0]), "+f"(c[1]), "+f"(c[2]), "+f"(c[3])
        : "r"(a[0]), "r"(a[1]), "r"(a[2]), "r"(a[3]), "r"(b[0]), "r"(b[1]));
}
__device__ __forceinline__ float2 ldnc_f2(const float* p) {
    float2 v;
    asm volatile("ld.global.nc.v2.f32 {%0, %1}, [%2];"
                 : "=f"(v.x), "=f"(v.y) : "l"(p));
    return v;
}
__device__ __forceinline__ uint4 ldcs_u4(const uint4* p) {
    uint4 v;
    asm volatile("ld.global.cs.v4.u32 {%0, %1, %2, %3}, [%4];"
                 : "=r"(v.x), "=r"(v.y), "=r"(v.z), "=r"(v.w) : "l"(p));
    return v;
}
__device__ __forceinline__ void stcs_u4(uint4* p, uint4 v) {
    asm volatile("st.global.cs.v4.u32 [%0], {%1, %2, %3, %4};"
                 :: "l"(p), "r"(v.x), "r"(v.y), "r"(v.z), "r"(v.w) : "memory");
}
__device__ __forceinline__ void stcs_f4(float4* p, float4 v) {
    asm volatile("st.global.cs.v4.f32 [%0], {%1, %2, %3, %4};"
                 :: "l"(p), "f"(v.x), "f"(v.y), "f"(v.z), "f"(v.w) : "memory");
}
__device__ __forceinline__ float sigm(float x) { return 1.f / (1.f + expf(-x)); }

// ========== bf16 GEMM: 128 threads, BM=128, BN=96, BK=64, 2-stage ==============
// Warp grid 2x2, warp tile 64x48. 64.5 KB smem, ~168 regs -> 3 CTAs/SM.
// Output: bf16, smem-staged coalesced uint4 stores, row stride Nstride (exact
// multiple of 96 tiles; no remap, no guard). Used for GI (stride H3) and
// logits (stride VP).
__global__ void __launch_bounds__(128, 3)
bf_gemm(const __nv_bfloat16* __restrict__ A, const __nv_bfloat16* __restrict__ W,
        const float* __restrict__ bias, __nv_bfloat16* __restrict__ Cb,
        int Nstride, int K) {
    constexpr int BM = 128, BN = 96;
    constexpr int RSTR = 36;                 // u32 per smem row (32 data + 4 pad)
    constexpr int ASTG = BM * RSTR;
    constexpr int BSTG = BN * RSTR;
    constexpr int STG = ASTG + BSTG;         // one stage (A then B)

    extern __shared__ uint32_t smu[];
    const uint32_t sS = smem_u32(smu);       // stage0 base; stage1 at +STG*4

    const int tid = threadIdx.x;
    const int wid = tid >> 5, lane = tid & 31;
    const int grp = lane >> 2, tig = lane & 3;
    const int warpRow = wid & 1, warpCol = wid >> 1;   // 2 x 2, warp tile 64x48
    const int mBase = blockIdx.y * BM;
    const int nBase = blockIdx.x * BN;

    auto load_stage = [&](int s, int kc) {
        const int k0 = kc * 64;
        const uint32_t base = sS + s * STG * 4;
#pragma unroll
        for (int i = 0; i < 8; i++) {                   // A: 1024 x 16B
            int idx = i * 128 + tid;
            int row = idx >> 3, c = idx & 7;
            cp_async16(base + (row * RSTR + c * 4) * 4,
                       A + (size_t)(mBase + row) * K + k0 + c * 8, 16);
        }
#pragma unroll
        for (int i = 0; i < 6; i++) {                   // B: 768 x 16B (N padded)
            int idx = i * 128 + tid;
            int row = idx >> 3, c = idx & 7;
            cp_async16(base + (ASTG + row * RSTR + c * 4) * 4,
                       W + (size_t)(nBase + row) * K + k0 + c * 8, 16);
        }
    };

    const int a_r = lane & 15, a_c = (lane >> 4) * 4;
    const int b_r = (lane >> 4) * 8 + (lane & 7), b_c = ((lane >> 3) & 1) * 4;
    uint32_t aOff[4], bOff[3];
#pragma unroll
    for (int mt = 0; mt < 4; mt++)
        aOff[mt] = ((warpRow * 64 + mt * 16 + a_r) * RSTR + a_c) * 4;
#pragma unroll
    for (int nb = 0; nb < 3; nb++)
        bOff[nb] = ((ASTG + (warpCol * 48 + nb * 16 + b_r) * RSTR + b_c)) * 4;

    float acc[4][6][4];
#pragma unroll
    for (int mt = 0; mt < 4; mt++)
#pragma unroll
        for (int nt = 0; nt < 6; nt++)
#pragma unroll
            for (int j = 0; j < 4; j++) acc[mt][nt][j] = 0.f;

    const int nk = K >> 6;
    load_stage(0, 0); cp_commit();
    load_stage(1, 1); cp_commit();

    for (int k = 0; k < nk; k++) {
        cp_wait1();                          // chunk k resident
        __syncthreads();
        const uint32_t st = sS + (k & 1) * STG * 4;
#pragma unroll
        for (int kk = 0; kk < 4; kk++) {     // four k16 slices (32B apart)
            uint32_t a[4][4], b[3][4];
#pragma unroll
            for (int mt = 0; mt < 4; mt++) ldm_x4(a[mt], st + aOff[mt] + kk * 32);
#pragma unroll
            for (int nb = 0; nb < 3; nb++) ldm_x4(b[nb], st + bOff[nb] + kk * 32);
#pragma unroll
            for (int mt = 0; mt < 4; mt++)
#pragma unroll
                for (int nt = 0; nt < 6; nt++)
                    mma_bf16(acc[mt][nt], a[mt], &b[nt >> 1][(nt & 1) * 2]);
        }
        __syncthreads();                     // all reads of buf k&1 done
        if (k + 2 < nk) { load_stage(k & 1, k + 2); }
        cp_commit();                         // keep group count in lockstep
    }

    // epilogue: bf16 tile staged in smem, then coalesced 16B stores
    constexpr int OSTR = 104;                // bf16 per row (208 B, 16B-aligned)
    __nv_bfloat16* ot = (__nv_bfloat16*)smu;
    __syncthreads();                         // mainloop smem free
#pragma unroll
    for (int mt = 0; mt < 4; mt++) {
        const int r0 = warpRow * 64 + mt * 16 + grp;
        const int r1 = r0 + 8;
#pragma unroll
        for (int nt = 0; nt < 6; nt++) {
            const int n = warpCol * 48 + nt * 8 + tig * 2;
            float2 bv = ldnc_f2(bias + nBase + n);
            *(uint32_t*)(ot + r0 * OSTR + n) =
                f2bf2(acc[mt][nt][0] + bv.x, acc[mt][nt][1] + bv.y);
            *(uint32_t*)(ot + r1 * OSTR + n) =
                f2bf2(acc[mt][nt][2] + bv.x, acc[mt][nt][3] + bv.y);
        }
    }
    __syncthreads();
#pragma unroll
    for (int i = 0; i < 12; i++) {           // 1536 uint4 = 128 rows x 12 chunks
        int idx = i * 128 + tid;
        int row = idx / 12, c = idx - row * 12;
        uint4 v = *(const uint4*)(ot + row * OSTR + c * 8);
        stcs_u4((uint4*)(Cb + (size_t)(mBase + row) * Nstride + nBase) + c, v);
    }
}

// ================== bf16 recurrence GEMM + fused GRU gates =====================
// BM=64, BN=96 ([r32|z32|n32]), BK=64; grid (16,16) = 256 CTAs, 69 KB smem.
__global__ void __launch_bounds__(256)
rec_step(const __nv_bfloat16* __restrict__ A, const __nv_bfloat16* __restrict__ W,
         const __nv_bfloat16* __restrict__ gi, const float* __restrict__ hpf,
         float* __restrict__ hout, __nv_bfloat16* __restrict__ hbf,
         const float* __restrict__ bhh) {
    constexpr int STAGES = 3, RSTR = 36;
    constexpr int ASTG = 64 * RSTR, BSTG = 96 * RSTR;
    constexpr int K = Hv;

    extern __shared__ uint32_t smu[];
    const uint32_t sA = smem_u32(smu);
    const uint32_t sB = sA + STAGES * ASTG * 4;

    const int tid = threadIdx.x;
    const int wid = tid >> 5, lane = tid & 31;
    const int grp = lane >> 2, tig = lane & 3;
    const int warpRow = wid >> 2, warpCol = wid & 3;   // 2 x 4, warp tile 32x24
    const int mBase = blockIdx.y * 64;
    const int nBase = blockIdx.x * 96;

    auto load_stage = [&](int s, int kc) {
        const int k0 = kc * 64;
#pragma unroll
        for (int i = 0; i < 2; i++) {                   // A: 512 x 16B
            int idx = i * 256 + tid;
            int row = idx >> 3, c = idx & 7;
            cp_async16(sA + (s * ASTG + row * RSTR + c * 4) * 4,
                       A + (size_t)(mBase + row) * K + k0 + c * 8, 16);
        }
#pragma unroll
        for (int i = 0; i < 3; i++) {                   // B: 768 x 16B
            int idx = i * 256 + tid;
            int row = idx >> 3, c = idx & 7;
            cp_async16(sB + (s * BSTG + row * RSTR + c * 4) * 4,
                       W + (size_t)(nBase + row) * K + k0 + c * 8, 16);
        }
    };

    const int a_r = lane & 15, a_c = (lane >> 4) * 4;
    const int b_r = (lane >> 4) * 8 + (lane & 7), b_c = ((lane >> 3) & 1) * 4;
    const int b2_r = lane & 7, b2_c = ((lane >> 3) & 1) * 4;   // x2 (lanes 0-15)
    uint32_t aOff[2], bOff, b2Off;
#pragma unroll
    for (int mt = 0; mt < 2; mt++)
        aOff[mt] = ((warpRow * 32 + mt * 16 + a_r) * RSTR + a_c) * 4;
    bOff  = ((warpCol * 24 + b_r) * RSTR + b_c) * 4;
    b2Off = ((warpCol * 24 + 16 + b2_r) * RSTR + b2_c) * 4;

    float acc[2][3][4];
#pragma unroll
    for (int mt = 0; mt < 2; mt++)
#pragma unroll
        for (int nt = 0; nt < 3; nt++)
#pragma unroll
            for (int j = 0; j < 4; j++) acc[mt][nt][j] = 0.f;

    const int nk = K >> 6;                    // 8
    load_stage(0, 0); cp_commit();
    load_stage(1, 1); cp_commit();

    for (int k = 0; k < nk; k++) {
        const int s = k % STAGES;
        cp_wait1();
        __syncthreads();
        if (k + 2 < nk) load_stage((k + 2) % STAGES, k + 2);
        cp_commit();

        const uint32_t aS = sA + s * ASTG * 4;
        const uint32_t bS = sB + s * BSTG * 4;
#pragma unroll
        for (int kk = 0; kk < 4; kk++) {
            uint32_t a[2][4], b01[4], b2[2];
#pragma unroll
            for (int mt = 0; mt < 2; mt++) ldm_x4(a[mt], aS + aOff[mt] + kk * 32);
            ldm_x4(b01, bS + bOff + kk * 32);
            ldm_x2(b2, bS + b2Off + kk * 32);
#pragma unroll
            for (int mt = 0; mt < 2; mt++) {
                mma_bf16(acc[mt][0], a[mt], &b01[0]);
                mma_bf16(acc[mt][1], a[mt], &b01[2]);
                mma_bf16(acc[mt][2], a[mt], b2);
            }
        }
    }

    // -------- epilogue: stage GH to smem, fused gate math --------
    constexpr int GSTR = 100;
    float* gh = (float*)smu;
    asm volatile("cp.async.wait_all;" ::: "memory");
    __syncthreads();
#pragma unroll
    for (int mt = 0; mt < 2; mt++) {
        const int r0 = warpRow * 32 + mt * 16 + grp;
#pragma unroll
        for (int nt = 0; nt < 3; nt++) {
            const int n = warpCol * 24 + nt * 8 + tig * 2;
            gh[r0 * GSTR + n] = acc[mt][nt][0];
            gh[r0 * GSTR + n + 1] = acc[mt][nt][1];
            gh[(r0 + 8) * GSTR + n] = acc[mt][nt][2];
            gh[(r0 + 8) * GSTR + n + 1] = acc[mt][nt][3];
        }
    }
    __syncthreads();
    const int qBase = nBase / 3;              // nBase = bx*96 -> q base = bx*32
#pragma unroll
    for (int i = 0; i < 8; i++) {
        const int idx = i * 256 + tid;        // 0..2047
        const int row = idx >> 5;
        const int q = idx & 31;
        const int m = mBase + row;
        const float ghr = gh[row * GSTR + q] + bhh[nBase + q];
        const float ghz = gh[row * GSTR + 32 + q] + bhh[nBase + 32 + q];
        const float ghn = gh[row * GSTR + 64 + q] + bhh[nBase + 64 + q];
        const __nv_bfloat16* girow = gi + (size_t)m * H3 + nBase;
        const float r = sigm(__bfloat162float(girow[q]) + ghr);
        const float z = sigm(__bfloat162float(girow[32 + q]) + ghz);
        const float n = tanhf(__bfloat162float(girow[64 + q]) + r * ghn);
        const int qg = qBase + q;
        const float hp = hpf[(size_t)m * Hv + qg];
        const float h = (1.f - z) * n + z * hp;
        hout[(size_t)m * Hv + qg] = h;
        hbf[(size_t)m * Hv + qg] = __float2bfloat16(h);
    }
}

// ---------------- prep kernels -------------------------------------------------
__global__ void gather_x(const float* __restrict__ embed,
                         const int* __restrict__ target) {
    int row = blockIdx.x;              // row = t*B + b
    int t = row >> 10;
    int b = row & (Bv - 1);
    int idx = (t == 0) ? 0 : target[b * Tv + (t - 1)];
    float4 v = ((const float4*)(embed + (size_t)idx * Ev))[threadIdx.x];
    uint2 o = make_uint2(f2bf2(v.x, v.y), f2bf2(v.z, v.w));
    ((uint2*)(g_Xb + (size_t)row * Ev))[threadIdx.x] = o;
}

__global__ void permute_w(const float* __restrict__ Wih, const float* __restrict__ Whh,
                          const float* __restrict__ bih, const float* __restrict__ bhh) {
    int p = blockIdx.x;                // 0..1535
    int T = p / 96, local = p - T * 96;
    int gate = local / 32, q = T * 32 + (local - gate * 32);
    int src = gate * Hv + q;
    int t = threadIdx.x;               // 128 threads
    if (t < 64) {
        float4 v = ((const float4*)(Wih + (size_t)src * Ev))[t];
        ((uint2*)(g_Wih_b + (size_t)p * Ev))[t] =
            make_uint2(f2bf2(v.x, v.y), f2bf2(v.z, v.w));
    }
    float4 w = ((const float4*)(Whh + (size_t)src * Hv))[t];
    ((uint2*)(g_Whh_b + (size_t)p * Hv))[t] =
        make_uint2(f2bf2(w.x, w.y), f2bf2(w.z, w.w));
    if (t == 0) { g_bih_p[p] = bih[src]; g_bhh_p[p] = bhh[src]; }
}

// convert out_W to bf16; zero-pad rows [Vv, VP)
__global__ void conv_outw(const float* __restrict__ W) {
    size_t i = ((size_t)blockIdx.x * 256 + threadIdx.x) * 4;   // over VP*Hv
    uint2 o = make_uint2(0u, 0u);
    if (i < (size_t)Vv * Hv) {
        float4 v = *(const float4*)(W + i);
        o = make_uint2(f2bf2(v.x, v.y), f2bf2(v.z, v.w));
    }
    *(uint2*)(g_Wout_b + i) = o;
}

__global__ void pad_bias(const float* __restrict__ b) {
    int i = blockIdx.x * 256 + threadIdx.x;
    if (i < VP) g_bout_p[i] = (i < Vv) ? b[i] : 0.f;
}

__global__ void conv_ctx(const float* __restrict__ ctx) {
    size_t i = ((size_t)blockIdx.x * 256 + threadIdx.x) * 4;
    float4 v = *(const float4*)(ctx + i);
    *(uint2*)(g_Hbf + i) = make_uint2(f2bf2(v.x, v.y), f2bf2(v.z, v.w));
}

// -------- log-softmax: bf16 logits (t*B+b rows) -> fp32 logprobs (b*T+t) -------
__global__ void __launch_bounds__(256)
logsoftmax_rows(const __nv_bfloat16* __restrict__ Lbf, float* __restrict__ out) {
    extern __shared__ float rowc[];     // 8000 floats
    __shared__ float sm[256], ss[256];
    const int tid = threadIdx.x;
    const int ro = blockIdx.x;          // output row (b*T + t)
    const int b = ro >> 4, t = ro & 15;
    const uint4* src = (const uint4*)(Lbf + (size_t)(t * Bv + b) * VP);

    float m = -INFINITY, s = 0.f;
    for (int i = tid; i < Vv / 8; i += 256) {      // 1000 x 16B loads
        uint4 u = ldcs_u4(src + i);
        float v[8];
        v[0] = __uint_as_float(u.x << 16); v[1] = __uint_as_float(u.x & 0xffff0000u);
        v[2] = __uint_as_float(u.y << 16); v[3] = __uint_as_float(u.y & 0xffff0000u);
        v[4] = __uint_as_float(u.z << 16); v[5] = __uint_as_float(u.z & 0xffff0000u);
        v[6] = __uint_as_float(u.w << 16); v[7] = __uint_as_float(u.w & 0xffff0000u);
        float mx = v[0];
#pragma unroll
        for (int j = 1; j < 8; j++) mx = fmaxf(mx, v[j]);
        if (mx > m) { s *= expf(m - mx); m = mx; }
#pragma unroll
        for (int j = 0; j < 8; j++) {
            rowc[8 * i + j] = v[j];
            s += expf(v[j] - m);
        }
    }
    sm[tid] = m; ss[tid] = s;
    __syncthreads();
    for (int st = 128; st > 0; st >>= 1) {
        if (tid < st) {
            float m2 = sm[tid + st], s2 = ss[tid + st];
            float M = fmaxf(sm[tid], m2);
            ss[tid] = ss[tid] * expf(sm[tid] - M) + s2 * expf(m2 - M);
            sm[tid] = M;
        }
        __syncthreads();
    }
    const float lse = sm[0] + logf(ss[0]);
    float4* dst = (float4*)(out + (size_t)ro * Vv);
    for (int i = tid; i < Vv / 4; i += 256) {
        float4 x = ((const float4*)rowc)[i];
        stcs_f4(dst + i, make_float4(x.x - lse, x.y - lse, x.z - lse, x.w - lse));
    }
}

// ---------------- launch --------------------------------------------------------
extern "C" void kernel_launch(void* const* d_in, const int* in_sizes, int n_in,
                              void* d_out, int out_size) {
    const float* context = (const float*)d_in[0];
    const int*   target  = (const int*)  d_in[1];
    const float* embed   = (const float*)d_in[2];
    const float* W_ih    = (const float*)d_in[3];
    const float* W_hh    = (const float*)d_in[4];
    const float* b_ih    = (const float*)d_in[5];
    const float* b_hh    = (const float*)d_in[6];
    const float* out_W   = (const float*)d_in[7];
    const float* out_b   = (const float*)d_in[8];
    float* out = (float*)d_out;

    float *pHall, *pbih, *pbhh, *pbout;
    __nv_bfloat16 *pXb, *pGIb, *pHbf, *pWihb, *pWhhb, *pWoutb, *pLbf;
    cudaGetSymbolAddress((void**)&pXb, g_Xb);
    cudaGetSymbolAddress((void**)&pGIb, g_GIb);
    cudaGetSymbolAddress((void**)&pHall, g_Hall);
    cudaGetSymbolAddress((void**)&pHbf, g_Hbf);
    cudaGetSymbolAddress((void**)&pWihb, g_Wih_b);
    cudaGetSymbolAddress((void**)&pWhhb, g_Whh_b);
    cudaGetSymbolAddress((void**)&pWoutb, g_Wout_b);
    cudaGetSymbolAddress((void**)&pLbf, g_Lbf);
    cudaGetSymbolAddress((void**)&pbih, g_bih_p);
    cudaGetSymbolAddress((void**)&pbhh, g_bhh_p);
    cudaGetSymbolAddress((void**)&pbout, g_bout_p);

    const int SMEMBF  = 2 * (128 + 96) * 36 * 4;    // 64512 -> 3 CTAs/SM
    const int SMEMREC = 3 * (64 + 96) * 36 * 4;     // 69120
    const int SMEMSFT = Vv * 4;                      // 32000
    cudaFuncSetAttribute(bf_gemm,
                         cudaFuncAttributeMaxDynamicSharedMemorySize, SMEMBF);
    cudaFuncSetAttribute(rec_step,
                         cudaFuncAttributeMaxDynamicSharedMemorySize, SMEMREC);
    cudaFuncSetAttribute(logsoftmax_rows,
                         cudaFuncAttributeMaxDynamicSharedMemorySize, SMEMSFT);

    // prep (GI = 4th launch -> lands in the ncu capture window)
    permute_w<<<H3, 128>>>(W_ih, W_hh, b_ih, b_hh);
    gather_x<<<Tv * Bv, 64>>>(embed, target);
    conv_ctx<<<(Bv * Hv) / 1024, 256>>>(context);

    // 1) GI (bf16 out) = X @ Wih^T + bih: (16384, 1536, K=256), grid (16, 128)
    bf_gemm<<<dim3(H3 / 96, (Tv * Bv) / 128), 128, SMEMBF>>>(
        pXb, pWihb, pbih, pGIb, H3, Ev);

    // 2) recurrence: 16 fused GEMM+gates launches (grid 16 x 16 = 256 CTAs)
    for (int t = 0; t < Tv; t++) {
        const float* hpf = (t == 0) ? context : (pHall + (size_t)(t - 1) * Bv * Hv);
        rec_step<<<dim3(H3 / 96, Bv / 64), 256, SMEMREC>>>(
            pHbf + (size_t)t * Bv * Hv, pWhhb, pGIb + (size_t)t * Bv * H3, hpf,
            pHall + (size_t)t * Bv * Hv, pHbf + (size_t)(t + 1) * Bv * Hv, pbhh);
    }

    // 3) out_W -> bf16 (zero-padded to VP rows); padded out_b
    conv_outw<<<(VP * Hv) / 1024, 256>>>(out_W);
    pad_bias<<<(VP + 255) / 256, 256>>>(out_b);

    // 4) logits (bf16 in, bf16 out staged via smem): grid (84, 128)
    bf_gemm<<<dim3(VP / 96, (Tv * Bv) / 128), 128, SMEMBF>>>(
        pHbf + (size_t)Bv * Hv, pWoutb, pbout, pLbf, VP, Hv);

    // 5) log-softmax: bf16 logits -> fp32 logprobs with (t,b)->(b,t) remap
    logsoftmax_rows<<<Bv * Tv, 256, SMEMSFT>>>(pLbf, out);
}